// round 1
// baseline (speedup 1.0000x reference)
#include <cuda_runtime.h>
#include <math.h>

#define GG 4
#define NN 50000
#define EE 800000
#define BB 32
#define FIN 64
#define HH 128
#define NHEADS 8
#define HD 16
#define GN (GG*NN)
#define GBH (GG*BB*HH)
#define NNODES 50000

// ---------------- scratch (device globals; no allocation allowed) -------------
__device__ float g_aggx[(size_t)GN*FIN];   // layer1 aggregated input (64-dim)
__device__ float g_a1[(size_t)GN*HH];      // relu(layer1)
__device__ float g_agg2[(size_t)GN*HH];    // layer2 aggregated
__device__ float g_a2[(size_t)GN*HH];      // relu(layer2)
__device__ float g_deg[GN];
__device__ float g_dinv[GN];
__device__ float g_embs[GBH];              // pooled sums
__device__ float g_cnt[GG*BB];
__device__ float g_emb[GBH];               // pooled means
__device__ float g_qkv[3*GBH];
__device__ float g_ctx[GBH];
__device__ float g_pooled[GG*HH];

__device__ __forceinline__ void red_add_v4(float* p, float4 v) {
    asm volatile("red.global.add.v4.f32 [%0], {%1, %2, %3, %4};"
        :: "l"(p), "f"(v.x), "f"(v.y), "f"(v.z), "f"(v.w) : "memory");
}

// ---------------- degree / norm ------------------------------------------------
__global__ void k_deg_init() {
    int i = blockIdx.x*blockDim.x + threadIdx.x;
    if (i < GN) g_deg[i] = 1.0f;   // self loop
}
__global__ void k_deg_acc(const int* __restrict__ ei) {
    int idx = blockIdx.x*blockDim.x + threadIdx.x;
    if (idx >= GG*EE) return;
    int g = idx / EE, e = idx - g*EE;
    int col = ei[(size_t)g*2*EE + EE + e];
    atomicAdd(&g_deg[g*NN + col], 1.0f);
}
__global__ void k_dinv() {
    int i = blockIdx.x*blockDim.x + threadIdx.x;
    if (i < GN) g_dinv[i] = rsqrtf(g_deg[i]);
}

// ---------------- self-loop init (also zero-initializes agg buffers) ------------
__global__ void k_self1(const float* __restrict__ x, int g) {
    int idx = blockIdx.x*blockDim.x + threadIdx.x;
    if (idx >= NN*(FIN/4)) return;
    int n = idx >> 4;                         // FIN/4 == 16
    float d = g_dinv[g*NN + n];
    float s = d*d;                            // 1/deg
    const float4* xs = (const float4*)(x + (size_t)g*NN*FIN);
    float4 v = xs[idx];
    ((float4*)g_aggx)[(size_t)g*NN*(FIN/4) + idx] =
        make_float4(v.x*s, v.y*s, v.z*s, v.w*s);
}
__global__ void k_self2(int g) {
    int idx = blockIdx.x*blockDim.x + threadIdx.x;
    if (idx >= NN*(HH/4)) return;
    int n = idx >> 5;                         // HH/4 == 32
    float d = g_dinv[g*NN + n];
    float s = d*d;
    const float4* a = (const float4*)g_a1 + (size_t)g*NN*(HH/4);
    float4 v = a[idx];
    ((float4*)g_agg2)[(size_t)g*NN*(HH/4) + idx] =
        make_float4(v.x*s, v.y*s, v.z*s, v.w*s);
}

// ---------------- edge scatter-gather -------------------------------------------
// layer 1: 2 edges per warp (64 floats each, 16 lanes x float4)
__global__ void k_edge1(const int* __restrict__ ei, const float* __restrict__ x, int g) {
    int w = blockIdx.x*8 + (threadIdx.x >> 5);
    int lane = threadIdx.x & 31;
    int e = w*2 + (lane >> 4);
    if (e >= EE) return;
    int sub = lane & 15;
    const int* bp = ei + (size_t)g*2*EE;
    int row = bp[e], col = bp[EE + e];
    float norm = g_dinv[g*NN + row] * g_dinv[g*NN + col];
    float4 v = *(const float4*)(x + ((size_t)(g*NN + row))*FIN + sub*4);
    red_add_v4(g_aggx + ((size_t)(g*NN + col))*FIN + sub*4,
               make_float4(v.x*norm, v.y*norm, v.z*norm, v.w*norm));
}
// layer 2: 1 edge per warp (128 floats, 32 lanes x float4)
__global__ void k_edge2(const int* __restrict__ ei, int g) {
    int e = blockIdx.x*8 + (threadIdx.x >> 5);
    if (e >= EE) return;
    int lane = threadIdx.x & 31;
    const int* bp = ei + (size_t)g*2*EE;
    int row = bp[e], col = bp[EE + e];
    float norm = g_dinv[g*NN + row] * g_dinv[g*NN + col];
    float4 v = *(const float4*)(g_a1 + ((size_t)(g*NN + row))*HH + lane*4);
    red_add_v4(g_agg2 + ((size_t)(g*NN + col))*HH + lane*4,
               make_float4(v.x*norm, v.y*norm, v.z*norm, v.w*norm));
}

// ---------------- dense [rows,K]@[K,128] + bias + relu ---------------------------
template<int K>
__global__ void __launch_bounds__(512) k_mm(const float* __restrict__ in,
        const float* __restrict__ W, const float* __restrict__ bias,
        float* __restrict__ out, int rows) {
    extern __shared__ float sm[];
    float* Wsm  = sm;             // K*128
    float* insm = sm + K*128;     // 32*K
    int tid = threadIdx.x;
    for (int idx = tid; idx < K*128; idx += 512) Wsm[idx] = W[idx];
    int base = blockIdx.x * 32;
    for (int idx = tid; idx < 32*K; idx += 512) {
        int t = idx / K; int kk = idx - t*K;
        int node = base + t;
        insm[idx] = (node < rows) ? in[(size_t)node*K + kk] : 0.0f;
    }
    __syncthreads();
    int c = tid & 127;
    int sub = tid >> 7;
    float bc = bias[c];
    float acc[8];
#pragma unroll
    for (int t = 0; t < 8; t++) acc[t] = bc;
    const float* ip = insm + sub*8*K;
#pragma unroll 4
    for (int k = 0; k < K; k += 4) {
        float w0 = Wsm[(k+0)*128 + c];
        float w1 = Wsm[(k+1)*128 + c];
        float w2 = Wsm[(k+2)*128 + c];
        float w3 = Wsm[(k+3)*128 + c];
#pragma unroll
        for (int t = 0; t < 8; t++) {
            float4 iv = *(const float4*)(ip + t*K + k);
            acc[t] = fmaf(iv.x, w0, acc[t]);
            acc[t] = fmaf(iv.y, w1, acc[t]);
            acc[t] = fmaf(iv.z, w2, acc[t]);
            acc[t] = fmaf(iv.w, w3, acc[t]);
        }
    }
#pragma unroll
    for (int t = 0; t < 8; t++) {
        int node = base + sub*8 + t;
        if (node < rows) out[(size_t)node*128 + c] = fmaxf(acc[t], 0.0f);
    }
}

// ---------------- mean pooling over (sorted) batch -------------------------------
__global__ void k_pool(const int* __restrict__ batch) {
    __shared__ float ssum[BB*HH];
    __shared__ float scnt[BB];
    int g = blockIdx.y;
    int tid = threadIdx.x;
    for (int i = tid; i < BB*HH; i += 128) ssum[i] = 0.0f;
    if (tid < BB) scnt[tid] = 0.0f;
    __syncthreads();
    int base = blockIdx.x*1024;
    int end = min(base + 1024, NN);
    const int* bt = batch + (size_t)g*NN;
    int prevb = bt[base];
    float acc = 0.0f, run = 0.0f;
    for (int n = base; n < end; n++) {
        int b = bt[n];
        float v = g_a2[((size_t)(g*NN + n))*HH + tid];
        if (b != prevb) {
            ssum[prevb*HH + tid] += acc;
            if (tid == 0) scnt[prevb] += run;
            acc = 0.0f; run = 0.0f; prevb = b;
        }
        acc += v; run += 1.0f;
    }
    ssum[prevb*HH + tid] += acc;
    if (tid == 0) scnt[prevb] += run;
    __syncthreads();
    for (int b = 0; b < BB; b++)
        atomicAdd(&g_embs[(g*BB + b)*HH + tid], ssum[b*HH + tid]);
    if (tid < BB) atomicAdd(&g_cnt[g*BB + tid], scnt[tid]);
}
__global__ void k_emb() {
    int idx = blockIdx.x*blockDim.x + threadIdx.x;
    if (idx >= GBH) return;
    float c = g_cnt[idx >> 7];
    g_emb[idx] = (c > 0.0f) ? g_embs[idx]/c : 0.0f;
}

// ---------------- attention -----------------------------------------------------
__global__ void k_qkv(const float* __restrict__ ipw, const float* __restrict__ ipb) {
    __shared__ float e[HH];
    int rowi = blockIdx.x;       // g*B+b
    int tid = threadIdx.x;       // 0..383
    if (tid < HH) e[tid] = g_emb[rowi*HH + tid];
    __syncthreads();
    float s = ipb[tid];
    const float* w = ipw + (size_t)tid*HH;
#pragma unroll 8
    for (int j = 0; j < HH; j++) s += e[j]*w[j];
    int sec = tid >> 7;
    int i = tid & 127;
    g_qkv[sec*GBH + rowi*HH + i] = s;
}
__global__ void k_attn() {
    int w = blockIdx.x*8 + (threadIdx.x >> 5);   // 0..255 = b*NHEADS+h
    int lane = threadIdx.x & 31;
    int b = w / NHEADS, h = w % NHEADS;
    const float* qp = g_qkv;
    const float* kp = g_qkv + GBH;
    const float* vp = g_qkv + 2*GBH;
    int gq = lane >> 2, kk = lane & 3;
    float s = 0.0f;
    if (lane < 16) {
        const float* qr = qp + (gq*BB + b)*HH + h*HD;
        const float* kr = kp + (kk*BB + b)*HH + h*HD;
#pragma unroll
        for (int d = 0; d < HD; d++) s += qr[d]*kr[d];
        s *= 0.25f;                      // 1/sqrt(16)
    }
    float m = s;
    m = fmaxf(m, __shfl_xor_sync(~0u, m, 1));
    m = fmaxf(m, __shfl_xor_sync(~0u, m, 2));
    float ev = expf(s - m);
    float sum = ev;
    sum += __shfl_xor_sync(~0u, sum, 1);
    sum += __shfl_xor_sync(~0u, sum, 2);
    float p = ev / sum;
    int g2 = lane >> 3, d0 = (lane & 7)*2;
    float c0 = 0.0f, c1 = 0.0f;
#pragma unroll
    for (int k2 = 0; k2 < 4; k2++) {
        float pv = __shfl_sync(~0u, p, g2*4 + k2);
        const float* vr = vp + (k2*BB + b)*HH + h*HD;
        c0 += pv*vr[d0];
        c1 += pv*vr[d0+1];
    }
    g_ctx[(g2*BB + b)*HH + h*HD + d0]     = c0;
    g_ctx[(g2*BB + b)*HH + h*HD + d0 + 1] = c1;
}
__global__ void k_attnout(const float* __restrict__ ow, const float* __restrict__ ob) {
    __shared__ float cs[HH];
    int g = blockIdx.x;
    int tid = threadIdx.x;
    float bo = ob[tid];
    float acc = 0.0f;
    for (int b = 0; b < BB; b++) {
        __syncthreads();
        cs[tid] = g_ctx[(g*BB + b)*HH + tid];
        __syncthreads();
        float s = bo;
        const float* wr = ow + (size_t)tid*HH;
#pragma unroll 8
        for (int j = 0; j < HH; j++) s += cs[j]*wr[j];
        acc += s;
    }
    g_pooled[g*HH + tid] = acc * (1.0f/BB);
}

// ---------------- final linear ----------------------------------------------------
__global__ void k_final(const float* __restrict__ lw, const float* __restrict__ lb,
                        float* __restrict__ out) {
    __shared__ float ps[GG*HH];
    int tid = threadIdx.x;
    for (int i = tid; i < GG*HH; i += 256) ps[i] = g_pooled[i];
    __syncthreads();
    int n = blockIdx.x*8 + (tid >> 5);
    if (n >= NNODES) return;
    int lane = tid & 31;
    float4 lv = *(const float4*)(lw + (size_t)n*HH + lane*4);
    float d[GG];
#pragma unroll
    for (int g = 0; g < GG; g++) {
        const float* pg = ps + g*HH + lane*4;
        d[g] = lv.x*pg[0] + lv.y*pg[1] + lv.z*pg[2] + lv.w*pg[3];
    }
#pragma unroll
    for (int g = 0; g < GG; g++)
        for (int off = 16; off; off >>= 1)
            d[g] += __shfl_xor_sync(~0u, d[g], off);
    if (lane == 0) {
        float bn = lb[n];
#pragma unroll
        for (int g = 0; g < GG; g++)
            out[(size_t)g*NNODES + n] = (d[g] + bn)*60.0f + 50.0f;
    }
}

// ---------------- launch ----------------------------------------------------------
extern "C" void kernel_launch(void* const* d_in, const int* in_sizes, int n_in,
                              void* d_out, int out_size) {
    const float* x   = (const float*)d_in[0];
    const int*   ei  = (const int*)  d_in[1];
    const int*   bat = (const int*)  d_in[2];
    const float* W1  = (const float*)d_in[3];
    const float* b1  = (const float*)d_in[4];
    const float* W2  = (const float*)d_in[5];
    const float* b2  = (const float*)d_in[6];
    const float* ipw = (const float*)d_in[7];
    const float* ipb = (const float*)d_in[8];
    const float* opw = (const float*)d_in[9];
    const float* opb = (const float*)d_in[10];
    const float* lw  = (const float*)d_in[11];
    const float* lb  = (const float*)d_in[12];
    float* out = (float*)d_out;

    float *p_aggx, *p_a1, *p_agg2, *p_a2, *p_embs, *p_cnt;
    cudaGetSymbolAddress((void**)&p_aggx, g_aggx);
    cudaGetSymbolAddress((void**)&p_a1,   g_a1);
    cudaGetSymbolAddress((void**)&p_agg2, g_agg2);
    cudaGetSymbolAddress((void**)&p_a2,   g_a2);
    cudaGetSymbolAddress((void**)&p_embs, g_embs);
    cudaGetSymbolAddress((void**)&p_cnt,  g_cnt);

    const int smem1 = (FIN*128 + 32*FIN)*4;   // 40 KB
    const int smem2 = (128*128 + 32*128)*4;   // 80 KB
    cudaFuncSetAttribute(k_mm<FIN>, cudaFuncAttributeMaxDynamicSharedMemorySize, smem1);
    cudaFuncSetAttribute(k_mm<128>, cudaFuncAttributeMaxDynamicSharedMemorySize, smem2);

    // degrees + normalization
    k_deg_init<<<(GN+255)/256, 256>>>();
    k_deg_acc<<<(GG*EE+255)/256, 256>>>(ei);
    k_dinv<<<(GN+255)/256, 256>>>();

    // layer 1: aggregate raw x (64-dim), then matmul+relu  (agg is linear => commutes with W1)
    for (int g = 0; g < GG; g++) {
        k_self1<<<(NN*(FIN/4)+255)/256, 256>>>(x, g);
        k_edge1<<<(EE/2 + 7)/8, 256>>>(ei, x, g);
    }
    k_mm<FIN><<<(GN+31)/32, 512, smem1>>>(p_aggx, W1, b1, p_a1, GN);

    // layer 2: aggregate a1 (128-dim), then matmul+relu
    for (int g = 0; g < GG; g++) {
        k_self2<<<(NN*(HH/4)+255)/256, 256>>>(g);
        k_edge2<<<(EE + 7)/8, 256>>>(ei, g);
    }
    k_mm<128><<<(GN+31)/32, 512, smem2>>>(p_agg2, W2, b2, p_a2, GN);

    // mean pooling per (graph, batch-bucket)
    cudaMemsetAsync(p_embs, 0, GBH*sizeof(float), 0);
    cudaMemsetAsync(p_cnt,  0, GG*BB*sizeof(float), 0);
    k_pool<<<dim3((NN+1023)/1024, GG), 128>>>(bat);
    k_emb<<<(GBH+255)/256, 256>>>();

    // attention + projections + mean over B
    k_qkv<<<GG*BB, 3*HH>>>(ipw, ipb);
    k_attn<<<32, 256>>>();
    k_attnout<<<GG, HH>>>(opw, opb);

    // final linear + affine
    k_final<<<(NNODES+7)/8, 256>>>(lw, lb, out);
}

// round 2
// speedup vs baseline: 1.2133x; 1.2133x over previous
#include <cuda_runtime.h>
#include <math.h>

#define GG 4
#define NN 50000
#define EE 800000
#define BB 32
#define FIN 64
#define HH 128
#define NHEADS 8
#define HD 16
#define GN (GG*NN)
#define GE (GG*EE)
#define GBH (GG*BB*HH)
#define NNODES 50000

// ---------------- scratch (device globals; no allocation allowed) -------------
__device__ float g_aggx[(size_t)GN*FIN];   // layer1 aggregated input (64-dim)
__device__ float g_a1[(size_t)GN*HH];      // relu(layer1)
__device__ float g_agg2[(size_t)GN*HH];    // layer2 aggregated
__device__ float g_a2[(size_t)GN*HH];      // relu(layer2)
__device__ int   g_degi[GN];
__device__ float g_dinv[GN];
__device__ int   g_off[GG*(NN+1)];
__device__ int   g_cur[GN];
__device__ int2  g_csr[(size_t)GE];        // packed {row, norm-as-int}
__device__ float g_embs[GBH];              // pooled sums
__device__ float g_cnt[GG*BB];
__device__ float g_emb[GBH];               // pooled means
__device__ float g_qkv[3*GBH];
__device__ float g_ctx[GBH];
__device__ float g_pooled[GG*HH];

// ---------------- CSR build ------------------------------------------------------
__global__ void k_count(const int* __restrict__ ei) {
    int idx = blockIdx.x*blockDim.x + threadIdx.x;
    if (idx >= GE) return;
    int g = idx / EE, e = idx - g*EE;
    int col = ei[(size_t)g*2*EE + EE + e];
    atomicAdd(&g_degi[g*NN + col], 1);
}

// per-graph exclusive prefix sum of degrees; also dinv and cursor init
__global__ void k_scan() {
    int g = blockIdx.x;
    int tid = threadIdx.x, lane = tid & 31, wid = tid >> 5;
    __shared__ int wtot[32];
    int run = 0;
    for (int base = 0; base < NN; base += 1024) {
        int i = base + tid;
        int c = (i < NN) ? g_degi[g*NN + i] : 0;
        int v = c;
#pragma unroll
        for (int o = 1; o < 32; o <<= 1) {
            int t = __shfl_up_sync(~0u, v, o);
            if (lane >= o) v += t;
        }
        if (lane == 31) wtot[wid] = v;
        __syncthreads();
        if (wid == 0) {
            int w2 = wtot[lane];
#pragma unroll
            for (int o = 1; o < 32; o <<= 1) {
                int t = __shfl_up_sync(~0u, w2, o);
                if (lane >= o) w2 += t;
            }
            wtot[lane] = w2;
        }
        __syncthreads();
        int excl = run + (wid > 0 ? wtot[wid-1] : 0) + v - c;
        if (i < NN) {
            g_off[g*(NN+1) + i] = excl;
            g_cur[g*NN + i] = excl;
            g_dinv[g*NN + i] = rsqrtf((float)(c + 1));
        }
        run += wtot[31];
        __syncthreads();
    }
    if (tid == 0) g_off[g*(NN+1) + NN] = run;
}

__global__ void k_fill(const int* __restrict__ ei) {
    int idx = blockIdx.x*blockDim.x + threadIdx.x;
    if (idx >= GE) return;
    int g = idx / EE, e = idx - g*EE;
    const int* bp = ei + (size_t)g*2*EE;
    int row = bp[e], col = bp[EE + e];
    float norm = g_dinv[g*NN + row] * g_dinv[g*NN + col];
    int pos = atomicAdd(&g_cur[g*NN + col], 1);
    g_csr[(size_t)g*EE + pos] = make_int2(row, __float_as_int(norm));
}

// ---------------- CSR gather aggregation ------------------------------------------
// layer 1: warp per node; lanes 0-15 / 16-31 handle alternating neighbors (64 floats)
__global__ void __launch_bounds__(256) k_g1(const float* __restrict__ x) {
    int w = blockIdx.x*8 + (threadIdx.x >> 5);
    if (w >= GN) return;
    int g = w / NN, n = w - g*NN;
    int lane = threadIdx.x & 31, sub = lane & 15, half = lane >> 4;
    const float* xg = x + (size_t)g*NN*FIN;
    float di = g_dinv[w], d2 = di*di;
    float4 acc = make_float4(0.f, 0.f, 0.f, 0.f);
    if (!half) {
        float4 v = *(const float4*)(xg + (size_t)n*FIN + sub*4);
        acc = make_float4(v.x*d2, v.y*d2, v.z*d2, v.w*d2);
    }
    int s = g_off[g*(NN+1) + n], e2 = g_off[g*(NN+1) + n + 1];
    const int2* cs = g_csr + (size_t)g*EE;
    for (int i = s + half; i < e2; i += 2) {
        int2 rn = __ldg(&cs[i]);
        float nr = __int_as_float(rn.y);
        float4 v = *(const float4*)(xg + (size_t)rn.x*FIN + sub*4);
        acc.x = fmaf(v.x, nr, acc.x);
        acc.y = fmaf(v.y, nr, acc.y);
        acc.z = fmaf(v.z, nr, acc.z);
        acc.w = fmaf(v.w, nr, acc.w);
    }
    acc.x += __shfl_xor_sync(~0u, acc.x, 16);
    acc.y += __shfl_xor_sync(~0u, acc.y, 16);
    acc.z += __shfl_xor_sync(~0u, acc.z, 16);
    acc.w += __shfl_xor_sync(~0u, acc.w, 16);
    if (!half) *(float4*)(g_aggx + (size_t)w*FIN + sub*4) = acc;
}

// layer 2: warp per node; full warp covers 128 floats; unroll 2 neighbors for MLP
__global__ void __launch_bounds__(256) k_g2() {
    int w = blockIdx.x*8 + (threadIdx.x >> 5);
    if (w >= GN) return;
    int g = w / NN, n = w - g*NN;
    int lane = threadIdx.x & 31;
    const float* ag = g_a1 + (size_t)g*NN*HH;
    float di = g_dinv[w], d2 = di*di;
    float4 v0 = *(const float4*)(ag + (size_t)n*HH + lane*4);
    float4 acc = make_float4(v0.x*d2, v0.y*d2, v0.z*d2, v0.w*d2);
    int s = g_off[g*(NN+1) + n], e2 = g_off[g*(NN+1) + n + 1];
    const int2* cs = g_csr + (size_t)g*EE;
    int i = s;
    for (; i + 1 < e2; i += 2) {
        int2 r0 = __ldg(&cs[i]);
        int2 r1 = __ldg(&cs[i+1]);
        float n0 = __int_as_float(r0.y), n1 = __int_as_float(r1.y);
        float4 a = *(const float4*)(ag + (size_t)r0.x*HH + lane*4);
        float4 b = *(const float4*)(ag + (size_t)r1.x*HH + lane*4);
        acc.x = fmaf(a.x, n0, fmaf(b.x, n1, acc.x));
        acc.y = fmaf(a.y, n0, fmaf(b.y, n1, acc.y));
        acc.z = fmaf(a.z, n0, fmaf(b.z, n1, acc.z));
        acc.w = fmaf(a.w, n0, fmaf(b.w, n1, acc.w));
    }
    if (i < e2) {
        int2 r0 = __ldg(&cs[i]);
        float n0 = __int_as_float(r0.y);
        float4 a = *(const float4*)(ag + (size_t)r0.x*HH + lane*4);
        acc.x = fmaf(a.x, n0, acc.x);
        acc.y = fmaf(a.y, n0, acc.y);
        acc.z = fmaf(a.z, n0, acc.z);
        acc.w = fmaf(a.w, n0, acc.w);
    }
    *(float4*)(g_agg2 + (size_t)w*HH + lane*4) = acc;
}

// ---------------- dense [rows,K]@[K,128] + bias + relu ---------------------------
template<int K>
__global__ void __launch_bounds__(512) k_mm(const float* __restrict__ in,
        const float* __restrict__ W, const float* __restrict__ bias,
        float* __restrict__ out, int rows) {
    extern __shared__ float sm[];
    float* Wsm  = sm;             // K*128
    float* insm = sm + K*128;     // 32*K
    int tid = threadIdx.x;
    for (int idx = tid; idx < K*128; idx += 512) Wsm[idx] = W[idx];
    int base = blockIdx.x * 32;
    for (int idx = tid; idx < 32*K; idx += 512) {
        int t = idx / K; int kk = idx - t*K;
        int node = base + t;
        insm[idx] = (node < rows) ? in[(size_t)node*K + kk] : 0.0f;
    }
    __syncthreads();
    int c = tid & 127;
    int sub = tid >> 7;
    float bc = bias[c];
    float acc[8];
#pragma unroll
    for (int t = 0; t < 8; t++) acc[t] = bc;
    const float* ip = insm + sub*8*K;
#pragma unroll 4
    for (int k = 0; k < K; k += 4) {
        float w0 = Wsm[(k+0)*128 + c];
        float w1 = Wsm[(k+1)*128 + c];
        float w2 = Wsm[(k+2)*128 + c];
        float w3 = Wsm[(k+3)*128 + c];
#pragma unroll
        for (int t = 0; t < 8; t++) {
            float4 iv = *(const float4*)(ip + t*K + k);
            acc[t] = fmaf(iv.x, w0, acc[t]);
            acc[t] = fmaf(iv.y, w1, acc[t]);
            acc[t] = fmaf(iv.z, w2, acc[t]);
            acc[t] = fmaf(iv.w, w3, acc[t]);
        }
    }
#pragma unroll
    for (int t = 0; t < 8; t++) {
        int node = base + sub*8 + t;
        if (node < rows) out[(size_t)node*128 + c] = fmaxf(acc[t], 0.0f);
    }
}

// ---------------- mean pooling over (sorted) batch -------------------------------
__global__ void k_pool(const int* __restrict__ batch) {
    __shared__ float ssum[BB*HH];
    __shared__ float scnt[BB];
    int g = blockIdx.y;
    int tid = threadIdx.x;
    for (int i = tid; i < BB*HH; i += 128) ssum[i] = 0.0f;
    if (tid < BB) scnt[tid] = 0.0f;
    __syncthreads();
    int base = blockIdx.x*1024;
    int end = min(base + 1024, NN);
    const int* bt = batch + (size_t)g*NN;
    int prevb = bt[base];
    float acc = 0.0f, run = 0.0f;
    for (int n = base; n < end; n++) {
        int b = bt[n];
        float v = g_a2[((size_t)(g*NN + n))*HH + tid];
        if (b != prevb) {
            ssum[prevb*HH + tid] += acc;
            if (tid == 0) scnt[prevb] += run;
            acc = 0.0f; run = 0.0f; prevb = b;
        }
        acc += v; run += 1.0f;
    }
    ssum[prevb*HH + tid] += acc;
    if (tid == 0) scnt[prevb] += run;
    __syncthreads();
    for (int b = 0; b < BB; b++)
        atomicAdd(&g_embs[(g*BB + b)*HH + tid], ssum[b*HH + tid]);
    if (tid < BB) atomicAdd(&g_cnt[g*BB + tid], scnt[tid]);
}
__global__ void k_emb() {
    int idx = blockIdx.x*blockDim.x + threadIdx.x;
    if (idx >= GBH) return;
    float c = g_cnt[idx >> 7];
    g_emb[idx] = (c > 0.0f) ? g_embs[idx]/c : 0.0f;
}

// ---------------- attention -----------------------------------------------------
__global__ void k_qkv(const float* __restrict__ ipw, const float* __restrict__ ipb) {
    __shared__ float e[HH];
    int rowi = blockIdx.x;       // g*B+b
    int tid = threadIdx.x;       // 0..383
    if (tid < HH) e[tid] = g_emb[rowi*HH + tid];
    __syncthreads();
    float s = ipb[tid];
    const float* w = ipw + (size_t)tid*HH;
#pragma unroll 8
    for (int j = 0; j < HH; j++) s += e[j]*w[j];
    int sec = tid >> 7;
    int i = tid & 127;
    g_qkv[sec*GBH + rowi*HH + i] = s;
}
__global__ void k_attn() {
    int w = blockIdx.x*8 + (threadIdx.x >> 5);   // 0..255 = b*NHEADS+h
    int lane = threadIdx.x & 31;
    int b = w / NHEADS, h = w % NHEADS;
    const float* qp = g_qkv;
    const float* kp = g_qkv + GBH;
    const float* vp = g_qkv + 2*GBH;
    int gq = lane >> 2, kk = lane & 3;
    float s = 0.0f;
    if (lane < 16) {
        const float* qr = qp + (gq*BB + b)*HH + h*HD;
        const float* kr = kp + (kk*BB + b)*HH + h*HD;
#pragma unroll
        for (int d = 0; d < HD; d++) s += qr[d]*kr[d];
        s *= 0.25f;                      // 1/sqrt(16)
    }
    float m = s;
    m = fmaxf(m, __shfl_xor_sync(~0u, m, 1));
    m = fmaxf(m, __shfl_xor_sync(~0u, m, 2));
    float ev = expf(s - m);
    float sum = ev;
    sum += __shfl_xor_sync(~0u, sum, 1);
    sum += __shfl_xor_sync(~0u, sum, 2);
    float p = ev / sum;
    int g2 = lane >> 3, d0 = (lane & 7)*2;
    float c0 = 0.0f, c1 = 0.0f;
#pragma unroll
    for (int k2 = 0; k2 < 4; k2++) {
        float pv = __shfl_sync(~0u, p, g2*4 + k2);
        const float* vr = vp + (k2*BB + b)*HH + h*HD;
        c0 += pv*vr[d0];
        c1 += pv*vr[d0+1];
    }
    g_ctx[(g2*BB + b)*HH + h*HD + d0]     = c0;
    g_ctx[(g2*BB + b)*HH + h*HD + d0 + 1] = c1;
}
__global__ void k_attnout(const float* __restrict__ ow, const float* __restrict__ ob) {
    __shared__ float cs[HH];
    int g = blockIdx.x;
    int tid = threadIdx.x;
    float bo = ob[tid];
    float acc = 0.0f;
    for (int b = 0; b < BB; b++) {
        __syncthreads();
        cs[tid] = g_ctx[(g*BB + b)*HH + tid];
        __syncthreads();
        float s = bo;
        const float* wr = ow + (size_t)tid*HH;
#pragma unroll 8
        for (int j = 0; j < HH; j++) s += cs[j]*wr[j];
        acc += s;
    }
    g_pooled[g*HH + tid] = acc * (1.0f/BB);
}

// ---------------- final linear ----------------------------------------------------
__global__ void k_final(const float* __restrict__ lw, const float* __restrict__ lb,
                        float* __restrict__ out) {
    __shared__ float ps[GG*HH];
    int tid = threadIdx.x;
    for (int i = tid; i < GG*HH; i += 256) ps[i] = g_pooled[i];
    __syncthreads();
    int n = blockIdx.x*8 + (tid >> 5);
    if (n >= NNODES) return;
    int lane = tid & 31;
    float4 lv = *(const float4*)(lw + (size_t)n*HH + lane*4);
    float d[GG];
#pragma unroll
    for (int g = 0; g < GG; g++) {
        const float* pg = ps + g*HH + lane*4;
        d[g] = lv.x*pg[0] + lv.y*pg[1] + lv.z*pg[2] + lv.w*pg[3];
    }
#pragma unroll
    for (int g = 0; g < GG; g++)
        for (int off = 16; off; off >>= 1)
            d[g] += __shfl_xor_sync(~0u, d[g], off);
    if (lane == 0) {
        float bn = lb[n];
#pragma unroll
        for (int g = 0; g < GG; g++)
            out[(size_t)g*NNODES + n] = (d[g] + bn)*60.0f + 50.0f;
    }
}

// ---------------- launch ----------------------------------------------------------
extern "C" void kernel_launch(void* const* d_in, const int* in_sizes, int n_in,
                              void* d_out, int out_size) {
    const float* x   = (const float*)d_in[0];
    const int*   ei  = (const int*)  d_in[1];
    const int*   bat = (const int*)  d_in[2];
    const float* W1  = (const float*)d_in[3];
    const float* b1  = (const float*)d_in[4];
    const float* W2  = (const float*)d_in[5];
    const float* b2  = (const float*)d_in[6];
    const float* ipw = (const float*)d_in[7];
    const float* ipb = (const float*)d_in[8];
    const float* opw = (const float*)d_in[9];
    const float* opb = (const float*)d_in[10];
    const float* lw  = (const float*)d_in[11];
    const float* lb  = (const float*)d_in[12];
    float* out = (float*)d_out;

    float *p_aggx, *p_a1, *p_agg2, *p_a2, *p_embs, *p_cnt;
    int *p_degi;
    cudaGetSymbolAddress((void**)&p_aggx, g_aggx);
    cudaGetSymbolAddress((void**)&p_a1,   g_a1);
    cudaGetSymbolAddress((void**)&p_agg2, g_agg2);
    cudaGetSymbolAddress((void**)&p_a2,   g_a2);
    cudaGetSymbolAddress((void**)&p_embs, g_embs);
    cudaGetSymbolAddress((void**)&p_cnt,  g_cnt);
    cudaGetSymbolAddress((void**)&p_degi, g_degi);

    const int smem1 = (FIN*128 + 32*FIN)*4;   // 40 KB
    const int smem2 = (128*128 + 32*128)*4;   // 80 KB
    cudaFuncSetAttribute(k_mm<FIN>, cudaFuncAttributeMaxDynamicSharedMemorySize, smem1);
    cudaFuncSetAttribute(k_mm<128>, cudaFuncAttributeMaxDynamicSharedMemorySize, smem2);

    // CSR build (shared by both layers)
    cudaMemsetAsync(p_degi, 0, GN*sizeof(int), 0);
    k_count<<<(GE+255)/256, 256>>>(ei);
    k_scan<<<GG, 1024>>>();
    k_fill<<<(GE+255)/256, 256>>>(ei);

    // layer 1: gather raw x (agg commutes with W1), then matmul+relu
    k_g1<<<(GN+7)/8, 256>>>(x);
    k_mm<FIN><<<(GN+31)/32, 512, smem1>>>(p_aggx, W1, b1, p_a1, GN);

    // layer 2: gather a1, then matmul+relu
    k_g2<<<(GN+7)/8, 256>>>();
    k_mm<128><<<(GN+31)/32, 512, smem2>>>(p_agg2, W2, b2, p_a2, GN);

    // mean pooling per (graph, batch-bucket)
    cudaMemsetAsync(p_embs, 0, GBH*sizeof(float), 0);
    cudaMemsetAsync(p_cnt,  0, GG*BB*sizeof(float), 0);
    k_pool<<<dim3((NN+1023)/1024, GG), 128>>>(bat);
    k_emb<<<(GBH+255)/256, 256>>>();

    // attention + projections + mean over B
    k_qkv<<<GG*BB, 3*HH>>>(ipw, ipb);
    k_attn<<<32, 256>>>();
    k_attnout<<<GG, HH>>>(opw, opb);

    // final linear + affine
    k_final<<<(NNODES+7)/8, 256>>>(lw, lb, out);
}

// round 3
// speedup vs baseline: 1.4024x; 1.1558x over previous
#include <cuda_runtime.h>
#include <cuda_fp16.h>
#include <math.h>

#define GG 4
#define NN 50000
#define EE 800000
#define BB 32
#define FIN 64
#define HH 128
#define NHEADS 8
#define HD 16
#define GN (GG*NN)
#define GE (GG*EE)
#define GBH (GG*BB*HH)
#define NNODES 50000
#define TILES 49   // ceil(NN/1024)

// ---------------- scratch (device globals; no allocation allowed) -------------
__device__ __half g_xh[(size_t)GN*FIN];    // fp16 copy of x
__device__ float g_aggx[(size_t)GN*FIN];   // layer1 aggregated input (fp32)
__device__ __half g_a1h[(size_t)GN*HH];    // relu(layer1) in fp16 (gather payload)
__device__ float g_agg2[(size_t)GN*HH];    // layer2 aggregated
__device__ float g_a2[(size_t)GN*HH];      // relu(layer2)
__device__ int   g_degi[GN];
__device__ float g_dinv[GN];
__device__ int   g_off[GG*(NN+1)];
__device__ int   g_cur[GN];
__device__ int   g_tsum[GG*TILES];
__device__ int   g_tbase[GG*TILES];
__device__ int2  g_csr[(size_t)GE];        // packed {row, norm-as-int}
__device__ int   g_bstart[GG*(BB+1)];
__device__ float g_emb[GBH];               // pooled means
__device__ float g_qkv[3*GBH];
__device__ float g_ctx[GBH];
__device__ float g_pooled[GG*HH];

// ---------------- x -> fp16 ------------------------------------------------------
__global__ void k_xcvt(const float* __restrict__ x) {
    size_t i = (size_t)blockIdx.x*blockDim.x + threadIdx.x;
    if (i >= (size_t)GN*FIN/8) return;
    const float4* xs = (const float4*)x;
    float4 f0 = xs[2*i], f1 = xs[2*i+1];
    __half2 h0 = __floats2half2_rn(f0.x, f0.y);
    __half2 h1 = __floats2half2_rn(f0.z, f0.w);
    __half2 h2 = __floats2half2_rn(f1.x, f1.y);
    __half2 h3 = __floats2half2_rn(f1.z, f1.w);
    uint4 o = make_uint4(*(unsigned*)&h0, *(unsigned*)&h1, *(unsigned*)&h2, *(unsigned*)&h3);
    ((uint4*)g_xh)[i] = o;
}

// ---------------- CSR build ------------------------------------------------------
__global__ void k_count(const int* __restrict__ ei) {
    int idx = blockIdx.x*blockDim.x + threadIdx.x;
    if (idx >= GE) return;
    int g = idx / EE, e = idx - g*EE;
    int col = ei[(size_t)g*2*EE + EE + e];
    atomicAdd(&g_degi[g*NN + col], 1);
}

// per-tile exclusive scan + dinv
__global__ void k_scan1() {
    int g = blockIdx.x / TILES, t = blockIdx.x % TILES;
    int tid = threadIdx.x, lane = tid & 31, wid = tid >> 5;
    __shared__ int wtot[32];
    int i = t*1024 + tid;
    int c = (i < NN) ? g_degi[g*NN + i] : 0;
    int v = c;
#pragma unroll
    for (int o = 1; o < 32; o <<= 1) {
        int u = __shfl_up_sync(~0u, v, o);
        if (lane >= o) v += u;
    }
    if (lane == 31) wtot[wid] = v;
    __syncthreads();
    if (wid == 0) {
        int w2 = wtot[lane];
#pragma unroll
        for (int o = 1; o < 32; o <<= 1) {
            int u = __shfl_up_sync(~0u, w2, o);
            if (lane >= o) w2 += u;
        }
        wtot[lane] = w2;
    }
    __syncthreads();
    int excl = (wid > 0 ? wtot[wid-1] : 0) + v - c;
    if (i < NN) {
        g_off[g*(NN+1) + i] = excl;
        g_dinv[g*NN + i] = rsqrtf((float)(c + 1));
    }
    if (tid == 0) g_tsum[blockIdx.x] = wtot[31];
}

// scan the 49 tile totals per graph (warp per graph)
__global__ void k_scan2() {
    int wid = threadIdx.x >> 5, lane = threadIdx.x & 31;
    if (wid >= GG) return;
    int v0 = g_tsum[wid*TILES + lane];            // lane < 32 <= TILES
    int v1 = (32 + lane < TILES) ? g_tsum[wid*TILES + 32 + lane] : 0;
    int s0 = v0;
#pragma unroll
    for (int o = 1; o < 32; o <<= 1) {
        int u = __shfl_up_sync(~0u, s0, o);
        if (lane >= o) s0 += u;
    }
    int tot0 = __shfl_sync(~0u, s0, 31);
    int s1 = v1;
#pragma unroll
    for (int o = 1; o < 32; o <<= 1) {
        int u = __shfl_up_sync(~0u, s1, o);
        if (lane >= o) s1 += u;
    }
    s1 += tot0;
    g_tbase[wid*TILES + lane] = s0 - v0;
    if (32 + lane < TILES) g_tbase[wid*TILES + 32 + lane] = s1 - v1;
}

__global__ void k_scan3() {
    int g = blockIdx.x / TILES, t = blockIdx.x % TILES;
    int i = t*1024 + threadIdx.x;
    if (i < NN) {
        int o = g_off[g*(NN+1) + i] + g_tbase[blockIdx.x];
        g_off[g*(NN+1) + i] = o;
        g_cur[g*NN + i] = o;
    }
    if (blockIdx.x == 0 && threadIdx.x < GG)
        g_off[threadIdx.x*(NN+1) + NN] = EE;
}

__global__ void k_fill(const int* __restrict__ ei) {
    int idx = blockIdx.x*blockDim.x + threadIdx.x;
    if (idx >= GE) return;
    int g = idx / EE, e = idx - g*EE;
    const int* bp = ei + (size_t)g*2*EE;
    int row = bp[e], col = bp[EE + e];
    float norm = g_dinv[g*NN + row] * g_dinv[g*NN + col];
    int pos = atomicAdd(&g_cur[g*NN + col], 1);
    g_csr[(size_t)g*EE + pos] = make_int2(row, __float_as_int(norm));
}

// ---------------- CSR gather aggregation (fp16 payload, fp32 accum) ---------------
// layer 1: warp per node; half-warps handle alternating neighbors (64 halfs = 128B)
__global__ void __launch_bounds__(256) k_g1() {
    int w = blockIdx.x*8 + (threadIdx.x >> 5);
    if (w >= GN) return;
    int g = w / NN, n = w - g*NN;
    int lane = threadIdx.x & 31, sub = lane & 15, half = lane >> 4;
    const __half* xg = g_xh + (size_t)g*NN*FIN;
    float di = g_dinv[w], d2 = di*di;
    float4 acc = make_float4(0.f, 0.f, 0.f, 0.f);
    if (!half) {
        uint2 hv = *(const uint2*)(xg + (size_t)n*FIN + sub*4);
        __half2 h0 = *(__half2*)&hv.x, h1 = *(__half2*)&hv.y;
        float2 f0 = __half22float2(h0), f1 = __half22float2(h1);
        acc = make_float4(f0.x*d2, f0.y*d2, f1.x*d2, f1.y*d2);
    }
    int s = g_off[g*(NN+1) + n], e2 = g_off[g*(NN+1) + n + 1];
    const int2* cs = g_csr + (size_t)g*EE;
    for (int i = s + half; i < e2; i += 2) {
        int2 rn = __ldg(&cs[i]);
        float nr = __int_as_float(rn.y);
        uint2 hv = *(const uint2*)(xg + (size_t)rn.x*FIN + sub*4);
        __half2 h0 = *(__half2*)&hv.x, h1 = *(__half2*)&hv.y;
        float2 f0 = __half22float2(h0), f1 = __half22float2(h1);
        acc.x = fmaf(f0.x, nr, acc.x);
        acc.y = fmaf(f0.y, nr, acc.y);
        acc.z = fmaf(f1.x, nr, acc.z);
        acc.w = fmaf(f1.y, nr, acc.w);
    }
    acc.x += __shfl_xor_sync(~0u, acc.x, 16);
    acc.y += __shfl_xor_sync(~0u, acc.y, 16);
    acc.z += __shfl_xor_sync(~0u, acc.z, 16);
    acc.w += __shfl_xor_sync(~0u, acc.w, 16);
    if (!half) *(float4*)(g_aggx + (size_t)w*FIN + sub*4) = acc;
}

// layer 2: warp per node; 128 halfs = 256B per row; unroll 2 neighbors
__global__ void __launch_bounds__(256) k_g2() {
    int w = blockIdx.x*8 + (threadIdx.x >> 5);
    if (w >= GN) return;
    int g = w / NN, n = w - g*NN;
    int lane = threadIdx.x & 31;
    const __half* ag = g_a1h + (size_t)g*NN*HH;
    float di = g_dinv[w], d2 = di*di;
    float4 acc;
    {
        uint2 hv = *(const uint2*)(ag + (size_t)n*HH + lane*4);
        __half2 h0 = *(__half2*)&hv.x, h1 = *(__half2*)&hv.y;
        float2 f0 = __half22float2(h0), f1 = __half22float2(h1);
        acc = make_float4(f0.x*d2, f0.y*d2, f1.x*d2, f1.y*d2);
    }
    int s = g_off[g*(NN+1) + n], e2 = g_off[g*(NN+1) + n + 1];
    const int2* cs = g_csr + (size_t)g*EE;
    int i = s;
    for (; i + 1 < e2; i += 2) {
        int2 r0 = __ldg(&cs[i]);
        int2 r1 = __ldg(&cs[i+1]);
        float n0 = __int_as_float(r0.y), n1 = __int_as_float(r1.y);
        uint2 ha = *(const uint2*)(ag + (size_t)r0.x*HH + lane*4);
        uint2 hb = *(const uint2*)(ag + (size_t)r1.x*HH + lane*4);
        __half2 a0 = *(__half2*)&ha.x, a1 = *(__half2*)&ha.y;
        __half2 b0 = *(__half2*)&hb.x, b1 = *(__half2*)&hb.y;
        float2 fa0 = __half22float2(a0), fa1 = __half22float2(a1);
        float2 fb0 = __half22float2(b0), fb1 = __half22float2(b1);
        acc.x = fmaf(fa0.x, n0, fmaf(fb0.x, n1, acc.x));
        acc.y = fmaf(fa0.y, n0, fmaf(fb0.y, n1, acc.y));
        acc.z = fmaf(fa1.x, n0, fmaf(fb1.x, n1, acc.z));
        acc.w = fmaf(fa1.y, n0, fmaf(fb1.y, n1, acc.w));
    }
    if (i < e2) {
        int2 r0 = __ldg(&cs[i]);
        float n0 = __int_as_float(r0.y);
        uint2 ha = *(const uint2*)(ag + (size_t)r0.x*HH + lane*4);
        __half2 a0 = *(__half2*)&ha.x, a1 = *(__half2*)&ha.y;
        float2 fa0 = __half22float2(a0), fa1 = __half22float2(a1);
        acc.x = fmaf(fa0.x, n0, acc.x);
        acc.y = fmaf(fa0.y, n0, acc.y);
        acc.z = fmaf(fa1.x, n0, acc.z);
        acc.w = fmaf(fa1.y, n0, acc.w);
    }
    *(float4*)(g_agg2 + (size_t)w*HH + lane*4) = acc;
}

// ---------------- dense [rows,K]@[K,128] + bias + relu ---------------------------
// HOUT: write fp16 into g_a1h instead of fp32 out.
template<int K, bool HOUT>
__global__ void __launch_bounds__(512) k_mm(const float* __restrict__ in,
        const float* __restrict__ W, const float* __restrict__ bias,
        float* __restrict__ out, int rows) {
    extern __shared__ float sm[];
    float* Wsm  = sm;             // K*128
    float* insm = sm + K*128;     // 32*K
    int tid = threadIdx.x;
    for (int idx = tid; idx < K*128; idx += 512) Wsm[idx] = W[idx];
    int base = blockIdx.x * 32;
    for (int idx = tid; idx < 32*K; idx += 512) {
        int t = idx / K; int kk = idx - t*K;
        int node = base + t;
        insm[idx] = (node < rows) ? in[(size_t)node*K + kk] : 0.0f;
    }
    __syncthreads();
    int c = tid & 127;
    int sub = tid >> 7;
    float bc = bias[c];
    float acc[8];
#pragma unroll
    for (int t = 0; t < 8; t++) acc[t] = bc;
    const float* ip = insm + sub*8*K;
#pragma unroll 4
    for (int k = 0; k < K; k += 4) {
        float w0 = Wsm[(k+0)*128 + c];
        float w1 = Wsm[(k+1)*128 + c];
        float w2 = Wsm[(k+2)*128 + c];
        float w3 = Wsm[(k+3)*128 + c];
#pragma unroll
        for (int t = 0; t < 8; t++) {
            float4 iv = *(const float4*)(ip + t*K + k);
            acc[t] = fmaf(iv.x, w0, acc[t]);
            acc[t] = fmaf(iv.y, w1, acc[t]);
            acc[t] = fmaf(iv.z, w2, acc[t]);
            acc[t] = fmaf(iv.w, w3, acc[t]);
        }
    }
#pragma unroll
    for (int t = 0; t < 8; t++) {
        int node = base + sub*8 + t;
        if (node < rows) {
            float r = fmaxf(acc[t], 0.0f);
            if (HOUT) g_a1h[(size_t)node*128 + c] = __float2half_rn(r);
            else      out[(size_t)node*128 + c] = r;
        }
    }
}

// ---------------- pooling: bucket bounds by binary search ------------------------
__global__ void k_bounds(const int* __restrict__ batch) {
    int tid = threadIdx.x;
    if (tid >= GG*BB) return;
    int g = tid >> 5, b = tid & 31;
    const int* bt = batch + (size_t)g*NN;
    int lo = 0, hi = NN;
    while (lo < hi) {
        int mid = (lo + hi) >> 1;
        if (bt[mid] < b) lo = mid + 1; else hi = mid;
    }
    g_bstart[g*(BB+1) + b] = lo;
    if (b == 0) g_bstart[g*(BB+1) + BB] = NN;
}

// one block per (g, bucket): mean over contiguous node range
__global__ void __launch_bounds__(256) k_pool2() {
    int g = blockIdx.x / BB, b = blockIdx.x % BB;
    int s = g_bstart[g*(BB+1) + b], e = g_bstart[g*(BB+1) + b + 1];
    int cnt = e - s;
    int tid = threadIdx.x;
    int cg = tid & 31, r0 = tid >> 5;         // 32 col-groups x 8 row-slots
    float4 acc = make_float4(0.f, 0.f, 0.f, 0.f);
    const float4* a2 = (const float4*)(g_a2 + (size_t)g*NN*HH);
    for (int n = s + r0; n < e; n += 8) {
        float4 v = a2[(size_t)n*32 + cg];
        acc.x += v.x; acc.y += v.y; acc.z += v.z; acc.w += v.w;
    }
    __shared__ float4 sacc[256];
    sacc[tid] = acc;
    __syncthreads();
    if (tid < 32) {
        float4 t = sacc[tid];
#pragma unroll
        for (int r = 1; r < 8; r++) {
            float4 o = sacc[tid + 32*r];
            t.x += o.x; t.y += o.y; t.z += o.z; t.w += o.w;
        }
        float inv = (cnt > 0) ? 1.0f/(float)cnt : 0.0f;
        *(float4*)(g_emb + (size_t)blockIdx.x*HH + tid*4) =
            make_float4(t.x*inv, t.y*inv, t.z*inv, t.w*inv);
    }
}

// ---------------- attention -----------------------------------------------------
__global__ void k_qkv(const float* __restrict__ ipw, const float* __restrict__ ipb) {
    __shared__ float e[HH];
    int rowi = blockIdx.x;       // g*B+b
    int tid = threadIdx.x;       // 0..383
    if (tid < HH) e[tid] = g_emb[rowi*HH + tid];
    __syncthreads();
    float s = ipb[tid];
    const float* w = ipw + (size_t)tid*HH;
#pragma unroll 8
    for (int j = 0; j < HH; j++) s += e[j]*w[j];
    int sec = tid >> 7;
    int i = tid & 127;
    g_qkv[sec*GBH + rowi*HH + i] = s;
}
__global__ void k_attn() {
    int w = blockIdx.x*8 + (threadIdx.x >> 5);   // 0..255 = b*NHEADS+h
    int lane = threadIdx.x & 31;
    int b = w / NHEADS, h = w % NHEADS;
    const float* qp = g_qkv;
    const float* kp = g_qkv + GBH;
    const float* vp = g_qkv + 2*GBH;
    int gq = lane >> 2, kk = lane & 3;
    float s = 0.0f;
    if (lane < 16) {
        const float* qr = qp + (gq*BB + b)*HH + h*HD;
        const float* kr = kp + (kk*BB + b)*HH + h*HD;
#pragma unroll
        for (int d = 0; d < HD; d++) s += qr[d]*kr[d];
        s *= 0.25f;                      // 1/sqrt(16)
    }
    float m = s;
    m = fmaxf(m, __shfl_xor_sync(~0u, m, 1));
    m = fmaxf(m, __shfl_xor_sync(~0u, m, 2));
    float ev = expf(s - m);
    float sum = ev;
    sum += __shfl_xor_sync(~0u, sum, 1);
    sum += __shfl_xor_sync(~0u, sum, 2);
    float p = ev / sum;
    int g2 = lane >> 3, d0 = (lane & 7)*2;
    float c0 = 0.0f, c1 = 0.0f;
#pragma unroll
    for (int k2 = 0; k2 < 4; k2++) {
        float pv = __shfl_sync(~0u, p, g2*4 + k2);
        const float* vr = vp + (k2*BB + b)*HH + h*HD;
        c0 += pv*vr[d0];
        c1 += pv*vr[d0+1];
    }
    g_ctx[(g2*BB + b)*HH + h*HD + d0]     = c0;
    g_ctx[(g2*BB + b)*HH + h*HD + d0 + 1] = c1;
}
__global__ void k_attnout(const float* __restrict__ ow, const float* __restrict__ ob) {
    __shared__ float cs[HH];
    int g = blockIdx.x;
    int tid = threadIdx.x;
    float bo = ob[tid];
    float acc = 0.0f;
    for (int b = 0; b < BB; b++) {
        __syncthreads();
        cs[tid] = g_ctx[(g*BB + b)*HH + tid];
        __syncthreads();
        float s = bo;
        const float* wr = ow + (size_t)tid*HH;
#pragma unroll 8
        for (int j = 0; j < HH; j++) s += cs[j]*wr[j];
        acc += s;
    }
    g_pooled[g*HH + tid] = acc * (1.0f/BB);
}

// ---------------- final linear ----------------------------------------------------
__global__ void k_final(const float* __restrict__ lw, const float* __restrict__ lb,
                        float* __restrict__ out) {
    __shared__ float ps[GG*HH];
    int tid = threadIdx.x;
    for (int i = tid; i < GG*HH; i += 256) ps[i] = g_pooled[i];
    __syncthreads();
    int n = blockIdx.x*8 + (tid >> 5);
    if (n >= NNODES) return;
    int lane = tid & 31;
    float4 lv = *(const float4*)(lw + (size_t)n*HH + lane*4);
    float d[GG];
#pragma unroll
    for (int g = 0; g < GG; g++) {
        const float* pg = ps + g*HH + lane*4;
        d[g] = lv.x*pg[0] + lv.y*pg[1] + lv.z*pg[2] + lv.w*pg[3];
    }
#pragma unroll
    for (int g = 0; g < GG; g++)
        for (int off = 16; off; off >>= 1)
            d[g] += __shfl_xor_sync(~0u, d[g], off);
    if (lane == 0) {
        float bn = lb[n];
#pragma unroll
        for (int g = 0; g < GG; g++)
            out[(size_t)g*NNODES + n] = (d[g] + bn)*60.0f + 50.0f;
    }
}

// ---------------- launch ----------------------------------------------------------
extern "C" void kernel_launch(void* const* d_in, const int* in_sizes, int n_in,
                              void* d_out, int out_size) {
    const float* x   = (const float*)d_in[0];
    const int*   ei  = (const int*)  d_in[1];
    const int*   bat = (const int*)  d_in[2];
    const float* W1  = (const float*)d_in[3];
    const float* b1  = (const float*)d_in[4];
    const float* W2  = (const float*)d_in[5];
    const float* b2  = (const float*)d_in[6];
    const float* ipw = (const float*)d_in[7];
    const float* ipb = (const float*)d_in[8];
    const float* opw = (const float*)d_in[9];
    const float* opb = (const float*)d_in[10];
    const float* lw  = (const float*)d_in[11];
    const float* lb  = (const float*)d_in[12];
    float* out = (float*)d_out;

    float *p_aggx, *p_agg2, *p_a2;
    int *p_degi;
    cudaGetSymbolAddress((void**)&p_aggx, g_aggx);
    cudaGetSymbolAddress((void**)&p_agg2, g_agg2);
    cudaGetSymbolAddress((void**)&p_a2,   g_a2);
    cudaGetSymbolAddress((void**)&p_degi, g_degi);

    const int smem1 = (FIN*128 + 32*FIN)*4;   // 40 KB
    const int smem2 = (128*128 + 32*128)*4;   // 80 KB
    cudaFuncSetAttribute(k_mm<FIN, true>,  cudaFuncAttributeMaxDynamicSharedMemorySize, smem1);
    cudaFuncSetAttribute(k_mm<128, false>, cudaFuncAttributeMaxDynamicSharedMemorySize, smem2);

    // x -> fp16 (independent of CSR build)
    k_xcvt<<<(GN*FIN/8 + 255)/256, 256>>>(x);

    // CSR build (shared by both layers)
    cudaMemsetAsync(p_degi, 0, GN*sizeof(int), 0);
    k_count<<<(GE+255)/256, 256>>>(ei);
    k_scan1<<<GG*TILES, 1024>>>();
    k_scan2<<<1, 128>>>();
    k_scan3<<<GG*TILES, 1024>>>();
    k_fill<<<(GE+255)/256, 256>>>(ei);

    // layer 1: gather fp16 x (agg commutes with W1), then matmul+relu -> fp16 a1
    k_g1<<<(GN+7)/8, 256>>>();
    k_mm<FIN, true><<<(GN+31)/32, 512, smem1>>>(p_aggx, W1, b1, nullptr, GN);

    // layer 2: gather fp16 a1, then matmul+relu -> fp32 a2
    k_g2<<<(GN+7)/8, 256>>>();
    k_mm<128, false><<<(GN+31)/32, 512, smem2>>>(p_agg2, W2, b2, p_a2, GN);

    // mean pooling per (graph, bucket) via sorted-bounds binary search
    k_bounds<<<1, 128>>>(bat);
    k_pool2<<<GG*BB, 256>>>();

    // attention + projections + mean over B
    k_qkv<<<GG*BB, 3*HH>>>(ipw, ipb);
    k_attn<<<32, 256>>>();
    k_attnout<<<GG, HH>>>(opw, opb);

    // final linear + affine
    k_final<<<(NNODES+7)/8, 256>>>(lw, lb, out);
}

// round 5
// speedup vs baseline: 2.0876x; 1.4886x over previous
#include <cuda_runtime.h>
#include <cuda_fp16.h>
#include <stdint.h>
#include <math.h>

#define GG 4
#define NN 50000
#define EE 800000
#define BB 32
#define FIN 64
#define HH 128
#define NHEADS 8
#define HD 16
#define GN (GG*NN)
#define GE (GG*EE)
#define GBH (GG*BB*HH)
#define NNODES 50000
#define TILES 49   // ceil(NN/1024)

// ---------------- scratch (device globals; no allocation allowed) -------------
__device__ __half g_xh[(size_t)GN*FIN];     // fp16 copy of x
__device__ __half g_aggxh[(size_t)GN*FIN];  // layer1 aggregated (fp16)
__device__ __half g_a1h[(size_t)GN*HH];     // relu(layer1) fp16
__device__ __half g_agg2h[(size_t)GN*HH];   // layer2 aggregated (fp16)
__device__ float g_a2[(size_t)GN*HH];       // relu(layer2) fp32
__device__ __half g_w1h[FIN*HH];
__device__ __half g_w2h[HH*HH];
__device__ int   g_degi[GN];
__device__ float g_dinv[GN];
__device__ int   g_off[GG*(NN+1)];
__device__ int   g_cur[GN];
__device__ int   g_tsum[GG*TILES];
__device__ int   g_tbase[GG*TILES];
__device__ int2  g_csr[(size_t)GE];         // packed {row, norm-as-int}
__device__ int   g_bstart[GG*(BB+1)];
__device__ float g_emb[GBH];                // pooled means
__device__ float g_qkv[3*GBH];
__device__ float g_ctx[GBH];
__device__ float g_pooled[GG*HH];

// ---------------- mma / ldmatrix helpers ------------------------------------------
__device__ __forceinline__ unsigned cvta_sm(const void* p) {
    return (unsigned)__cvta_generic_to_shared(p);
}
__device__ __forceinline__ void ldmx4(unsigned& r0, unsigned& r1, unsigned& r2, unsigned& r3, unsigned a) {
    asm volatile("ldmatrix.sync.aligned.m8n8.x4.shared.b16 {%0,%1,%2,%3},[%4];"
        : "=r"(r0), "=r"(r1), "=r"(r2), "=r"(r3) : "r"(a));
}
__device__ __forceinline__ void ldmx4t(unsigned& r0, unsigned& r1, unsigned& r2, unsigned& r3, unsigned a) {
    asm volatile("ldmatrix.sync.aligned.m8n8.x4.trans.shared.b16 {%0,%1,%2,%3},[%4];"
        : "=r"(r0), "=r"(r1), "=r"(r2), "=r"(r3) : "r"(a));
}
__device__ __forceinline__ void mma16816(float* d, unsigned a0, unsigned a1, unsigned a2, unsigned a3,
                                         unsigned b0, unsigned b1) {
    asm volatile("mma.sync.aligned.m16n8k16.row.col.f32.f16.f16.f32 "
        "{%0,%1,%2,%3},{%4,%5,%6,%7},{%8,%9},{%0,%1,%2,%3};"
        : "+f"(d[0]), "+f"(d[1]), "+f"(d[2]), "+f"(d[3])
        : "r"(a0), "r"(a1), "r"(a2), "r"(a3), "r"(b0), "r"(b1));
}

// ---------------- conversions ------------------------------------------------------
__global__ void k_xcvt(const float* __restrict__ x) {
    size_t i = (size_t)blockIdx.x*blockDim.x + threadIdx.x;
    if (i >= (size_t)GN*FIN/8) return;
    const float4* xs = (const float4*)x;
    float4 f0 = xs[2*i], f1 = xs[2*i+1];
    __half2 h0 = __floats2half2_rn(f0.x, f0.y);
    __half2 h1 = __floats2half2_rn(f0.z, f0.w);
    __half2 h2 = __floats2half2_rn(f1.x, f1.y);
    __half2 h3 = __floats2half2_rn(f1.z, f1.w);
    uint4 o = make_uint4(*(unsigned*)&h0, *(unsigned*)&h1, *(unsigned*)&h2, *(unsigned*)&h3);
    ((uint4*)g_xh)[i] = o;
}
__global__ void k_wcvt(const float* __restrict__ W1, const float* __restrict__ W2) {
    int i = blockIdx.x*blockDim.x + threadIdx.x;
    if (i < FIN*HH) g_w1h[i] = __float2half_rn(W1[i]);
    if (i < HH*HH)  g_w2h[i] = __float2half_rn(W2[i]);
}

// ---------------- CSR build ------------------------------------------------------
__global__ void k_count(const int* __restrict__ ei) {
    int idx = blockIdx.x*blockDim.x + threadIdx.x;
    if (idx >= GE) return;
    int g = idx / EE, e = idx - g*EE;
    int col = ei[(size_t)g*2*EE + EE + e];
    atomicAdd(&g_degi[g*NN + col], 1);
}
__global__ void k_scan1() {
    int g = blockIdx.x / TILES, t = blockIdx.x % TILES;
    int tid = threadIdx.x, lane = tid & 31, wid = tid >> 5;
    __shared__ int wtot[32];
    int i = t*1024 + tid;
    int c = (i < NN) ? g_degi[g*NN + i] : 0;
    int v = c;
#pragma unroll
    for (int o = 1; o < 32; o <<= 1) {
        int u = __shfl_up_sync(~0u, v, o);
        if (lane >= o) v += u;
    }
    if (lane == 31) wtot[wid] = v;
    __syncthreads();
    if (wid == 0) {
        int w2 = wtot[lane];
#pragma unroll
        for (int o = 1; o < 32; o <<= 1) {
            int u = __shfl_up_sync(~0u, w2, o);
            if (lane >= o) w2 += u;
        }
        wtot[lane] = w2;
    }
    __syncthreads();
    int excl = (wid > 0 ? wtot[wid-1] : 0) + v - c;
    if (i < NN) {
        g_off[g*(NN+1) + i] = excl;
        g_dinv[g*NN + i] = rsqrtf((float)(c + 1));
    }
    if (tid == 0) g_tsum[blockIdx.x] = wtot[31];
}
__global__ void k_scan2() {
    int wid = threadIdx.x >> 5, lane = threadIdx.x & 31;
    if (wid >= GG) return;
    int v0 = g_tsum[wid*TILES + lane];
    int v1 = (32 + lane < TILES) ? g_tsum[wid*TILES + 32 + lane] : 0;
    int s0 = v0;
#pragma unroll
    for (int o = 1; o < 32; o <<= 1) {
        int u = __shfl_up_sync(~0u, s0, o);
        if (lane >= o) s0 += u;
    }
    int tot0 = __shfl_sync(~0u, s0, 31);
    int s1 = v1;
#pragma unroll
    for (int o = 1; o < 32; o <<= 1) {
        int u = __shfl_up_sync(~0u, s1, o);
        if (lane >= o) s1 += u;
    }
    s1 += tot0;
    g_tbase[wid*TILES + lane] = s0 - v0;
    if (32 + lane < TILES) g_tbase[wid*TILES + 32 + lane] = s1 - v1;
}
__global__ void k_scan3() {
    int g = blockIdx.x / TILES, t = blockIdx.x % TILES;
    int i = t*1024 + threadIdx.x;
    if (i < NN) {
        int o = g_off[g*(NN+1) + i] + g_tbase[blockIdx.x];
        g_off[g*(NN+1) + i] = o;
        g_cur[g*NN + i] = o;
    }
    if (blockIdx.x == 0 && threadIdx.x < GG)
        g_off[threadIdx.x*(NN+1) + NN] = EE;
}
__global__ void k_fill(const int* __restrict__ ei) {
    int idx = blockIdx.x*blockDim.x + threadIdx.x;
    if (idx >= GE) return;
    int g = idx / EE, e = idx - g*EE;
    const int* bp = ei + (size_t)g*2*EE;
    int row = bp[e], col = bp[EE + e];
    float norm = g_dinv[g*NN + row] * g_dinv[g*NN + col];
    int pos = atomicAdd(&g_cur[g*NN + col], 1);
    g_csr[(size_t)g*EE + pos] = make_int2(row, __float_as_int(norm));
}

// ---------------- CSR gather aggregation (fp16 payload + fp16 out) -----------------
__device__ __forceinline__ float4 h4ld(const __half* p) {
    uint2 hv = *(const uint2*)p;
    __half2 h0 = *(__half2*)&hv.x, h1 = *(__half2*)&hv.y;
    float2 f0 = __half22float2(h0), f1 = __half22float2(h1);
    return make_float4(f0.x, f0.y, f1.x, f1.y);
}
__device__ __forceinline__ void h4st(__half* p, float4 v) {
    __half2 h0 = __floats2half2_rn(v.x, v.y);
    __half2 h1 = __floats2half2_rn(v.z, v.w);
    uint2 o = make_uint2(*(unsigned*)&h0, *(unsigned*)&h1);
    *(uint2*)p = o;
}

// layer 1: warp per node; half-warps alternate neighbors; 2-unroll per half
__global__ void __launch_bounds__(256) k_g1() {
    int w = blockIdx.x*8 + (threadIdx.x >> 5);
    if (w >= GN) return;
    int g = w / NN, n = w - g*NN;
    int lane = threadIdx.x & 31, sub = lane & 15, half = lane >> 4;
    const __half* xg = g_xh + (size_t)g*NN*FIN;
    float di = g_dinv[w], d2 = di*di;
    float4 acc = make_float4(0.f, 0.f, 0.f, 0.f);
    if (!half) {
        float4 v = h4ld(xg + (size_t)n*FIN + sub*4);
        acc = make_float4(v.x*d2, v.y*d2, v.z*d2, v.w*d2);
    }
    int s = g_off[g*(NN+1) + n], e2 = g_off[g*(NN+1) + n + 1];
    const int2* cs = g_csr + (size_t)g*EE;
    int i = s + half;
    for (; i + 2 < e2; i += 4) {
        int2 r0 = __ldg(&cs[i]);
        int2 r1 = __ldg(&cs[i+2]);
        float n0 = __int_as_float(r0.y), n1 = __int_as_float(r1.y);
        float4 a = h4ld(xg + (size_t)r0.x*FIN + sub*4);
        float4 b = h4ld(xg + (size_t)r1.x*FIN + sub*4);
        acc.x = fmaf(a.x, n0, fmaf(b.x, n1, acc.x));
        acc.y = fmaf(a.y, n0, fmaf(b.y, n1, acc.y));
        acc.z = fmaf(a.z, n0, fmaf(b.z, n1, acc.z));
        acc.w = fmaf(a.w, n0, fmaf(b.w, n1, acc.w));
    }
    if (i < e2) {
        int2 r0 = __ldg(&cs[i]);
        float n0 = __int_as_float(r0.y);
        float4 a = h4ld(xg + (size_t)r0.x*FIN + sub*4);
        acc.x = fmaf(a.x, n0, acc.x);
        acc.y = fmaf(a.y, n0, acc.y);
        acc.z = fmaf(a.z, n0, acc.z);
        acc.w = fmaf(a.w, n0, acc.w);
    }
    acc.x += __shfl_xor_sync(~0u, acc.x, 16);
    acc.y += __shfl_xor_sync(~0u, acc.y, 16);
    acc.z += __shfl_xor_sync(~0u, acc.z, 16);
    acc.w += __shfl_xor_sync(~0u, acc.w, 16);
    if (!half) h4st(g_aggxh + (size_t)w*FIN + sub*4, acc);
}

// layer 2: warp per node; 4-unroll
__global__ void __launch_bounds__(256) k_g2() {
    int w = blockIdx.x*8 + (threadIdx.x >> 5);
    if (w >= GN) return;
    int g = w / NN, n = w - g*NN;
    int lane = threadIdx.x & 31;
    const __half* ag = g_a1h + (size_t)g*NN*HH;
    float di = g_dinv[w], d2 = di*di;
    float4 v0 = h4ld(ag + (size_t)n*HH + lane*4);
    float4 acc = make_float4(v0.x*d2, v0.y*d2, v0.z*d2, v0.w*d2);
    int s = g_off[g*(NN+1) + n], e2 = g_off[g*(NN+1) + n + 1];
    const int2* cs = g_csr + (size_t)g*EE;
    int i = s;
    for (; i + 3 < e2; i += 4) {
        int2 r0 = __ldg(&cs[i]);
        int2 r1 = __ldg(&cs[i+1]);
        int2 r2 = __ldg(&cs[i+2]);
        int2 r3 = __ldg(&cs[i+3]);
        float4 a = h4ld(ag + (size_t)r0.x*HH + lane*4);
        float4 b = h4ld(ag + (size_t)r1.x*HH + lane*4);
        float4 c = h4ld(ag + (size_t)r2.x*HH + lane*4);
        float4 d = h4ld(ag + (size_t)r3.x*HH + lane*4);
        float n0 = __int_as_float(r0.y), n1 = __int_as_float(r1.y);
        float n2 = __int_as_float(r2.y), n3 = __int_as_float(r3.y);
        acc.x = fmaf(a.x, n0, fmaf(b.x, n1, fmaf(c.x, n2, fmaf(d.x, n3, acc.x))));
        acc.y = fmaf(a.y, n0, fmaf(b.y, n1, fmaf(c.y, n2, fmaf(d.y, n3, acc.y))));
        acc.z = fmaf(a.z, n0, fmaf(b.z, n1, fmaf(c.z, n2, fmaf(d.z, n3, acc.z))));
        acc.w = fmaf(a.w, n0, fmaf(b.w, n1, fmaf(c.w, n2, fmaf(d.w, n3, acc.w))));
    }
    for (; i < e2; i++) {
        int2 r0 = __ldg(&cs[i]);
        float n0 = __int_as_float(r0.y);
        float4 a = h4ld(ag + (size_t)r0.x*HH + lane*4);
        acc.x = fmaf(a.x, n0, acc.x);
        acc.y = fmaf(a.y, n0, acc.y);
        acc.z = fmaf(a.z, n0, acc.z);
        acc.w = fmaf(a.w, n0, acc.w);
    }
    h4st(g_agg2h + (size_t)w*HH + lane*4, acc);
}

// ---------------- tensor-core matmul: relu(in[rows,K] @ W[K,128] + b) --------------
// 256 threads = 8 warps; block tile 128 rows x 128 cols; fp16 in, fp32 accum.
template<int K, bool HOUT>
__global__ void __launch_bounds__(256) k_mmt(const __half* __restrict__ in,
        const __half* __restrict__ Wh, const float* __restrict__ bias,
        float* __restrict__ out, int rows) {
    constexpr int AS = K + 8;      // padded A row (halfs): odd 16B-unit stride
    constexpr int WS = HH + 8;     // 136
    extern __shared__ __half smh[];
    __half* As = smh;              // 128 * AS
    __half* Ws = smh + 128*AS;     // K * WS
    int tid = threadIdx.x;
    int wid = tid >> 5, lane = tid & 31;
    int base = blockIdx.x * 128;

    // load W tile (K x 128) -> Ws
    for (int idx = tid; idx < K*16; idx += 256) {
        int r = idx >> 4, c8 = (idx & 15) << 3;
        *(uint4*)(Ws + r*WS + c8) = *(const uint4*)(Wh + r*HH + c8);
    }
    // load A tile (128 x K) -> As (zero-pad OOB rows)
    for (int idx = tid; idx < 128*(K/8); idx += 256) {
        int r = idx/(K/8), c8 = (idx%(K/8))*8;
        int node = base + r;
        uint4 v = make_uint4(0u,0u,0u,0u);
        if (node < rows) v = *(const uint4*)(in + (size_t)node*K + c8);
        *(uint4*)(As + r*AS + c8) = v;
    }
    __syncthreads();

    float d[16][4];
#pragma unroll
    for (int t = 0; t < 16; t++) {
        d[t][0] = 0.f; d[t][1] = 0.f; d[t][2] = 0.f; d[t][3] = 0.f;
    }

    unsigned a_sm = cvta_sm(As);
    unsigned w_sm = cvta_sm(Ws);
    int arow = wid*16 + (lane & 15);
    int asel = (lane >> 4) * 8;
    int krow = lane & 15;

    for (int kk = 0; kk < K/16; kk++) {
        unsigned a0, a1, a2, a3;
        ldmx4(a0, a1, a2, a3, a_sm + (unsigned)(arow*AS + kk*16 + asel)*2u);
#pragma unroll
        for (int nt = 0; nt < 8; nt++) {
            unsigned b0, b1, b2, b3;
            ldmx4t(b0, b1, b2, b3, w_sm + (unsigned)((kk*16 + krow)*WS + nt*16 + asel)*2u);
            mma16816(d[2*nt],   a0, a1, a2, a3, b0, b1);
            mma16816(d[2*nt+1], a0, a1, a2, a3, b2, b3);
        }
    }

    // epilogue: bias + relu + store
    int gq = lane >> 2, tq = lane & 3;
    int row0 = base + wid*16 + gq;
    int row1 = row0 + 8;
#pragma unroll
    for (int nt = 0; nt < 16; nt++) {
        int c0 = nt*8 + tq*2;
        float2 bc = *(const float2*)(bias + c0);
        float v00 = fmaxf(d[nt][0] + bc.x, 0.f);
        float v01 = fmaxf(d[nt][1] + bc.y, 0.f);
        float v10 = fmaxf(d[nt][2] + bc.x, 0.f);
        float v11 = fmaxf(d[nt][3] + bc.y, 0.f);
        if (HOUT) {
            __half2 h0 = __floats2half2_rn(v00, v01);
            __half2 h1 = __floats2half2_rn(v10, v11);
            if (row0 < rows) *(unsigned*)(g_a1h + (size_t)row0*HH + c0) = *(unsigned*)&h0;
            if (row1 < rows) *(unsigned*)(g_a1h + (size_t)row1*HH + c0) = *(unsigned*)&h1;
        } else {
            if (row0 < rows) *(float2*)(out + (size_t)row0*HH + c0) = make_float2(v00, v01);
            if (row1 < rows) *(float2*)(out + (size_t)row1*HH + c0) = make_float2(v10, v11);
        }
    }
}

// ---------------- pooling --------------------------------------------------------
__global__ void k_bounds(const int* __restrict__ batch) {
    int tid = threadIdx.x;
    if (tid >= GG*BB) return;
    int g = tid >> 5, b = tid & 31;
    const int* bt = batch + (size_t)g*NN;
    int lo = 0, hi = NN;
    while (lo < hi) {
        int mid = (lo + hi) >> 1;
        if (bt[mid] < b) lo = mid + 1; else hi = mid;
    }
    g_bstart[g*(BB+1) + b] = lo;
    if (b == 0) g_bstart[g*(BB+1) + BB] = NN;
}
__global__ void __launch_bounds__(256) k_pool2() {
    int g = blockIdx.x / BB, b = blockIdx.x % BB;
    int s = g_bstart[g*(BB+1) + b], e = g_bstart[g*(BB+1) + b + 1];
    int cnt = e - s;
    int tid = threadIdx.x;
    int cg = tid & 31, r0 = tid >> 5;
    float4 acc = make_float4(0.f, 0.f, 0.f, 0.f);
    const float4* a2 = (const float4*)(g_a2 + (size_t)g*NN*HH);
    for (int n = s + r0; n < e; n += 8) {
        float4 v = a2[(size_t)n*32 + cg];
        acc.x += v.x; acc.y += v.y; acc.z += v.z; acc.w += v.w;
    }
    __shared__ float4 sacc[256];
    sacc[tid] = acc;
    __syncthreads();
    if (tid < 32) {
        float4 t = sacc[tid];
#pragma unroll
        for (int r = 1; r < 8; r++) {
            float4 o = sacc[tid + 32*r];
            t.x += o.x; t.y += o.y; t.z += o.z; t.w += o.w;
        }
        float inv = (cnt > 0) ? 1.0f/(float)cnt : 0.0f;
        *(float4*)(g_emb + (size_t)blockIdx.x*HH + tid*4) =
            make_float4(t.x*inv, t.y*inv, t.z*inv, t.w*inv);
    }
}

// ---------------- attention -------------------------------------------------------
__global__ void k_qkv(const float* __restrict__ ipw, const float* __restrict__ ipb) {
    __shared__ float e[HH];
    int rowi = blockIdx.x;
    int tid = threadIdx.x;
    if (tid < HH) e[tid] = g_emb[rowi*HH + tid];
    __syncthreads();
    float s = ipb[tid];
    const float* w = ipw + (size_t)tid*HH;
#pragma unroll 8
    for (int j = 0; j < HH; j++) s += e[j]*w[j];
    int sec = tid >> 7;
    int i = tid & 127;
    g_qkv[sec*GBH + rowi*HH + i] = s;
}
__global__ void k_attn() {
    int w = blockIdx.x*8 + (threadIdx.x >> 5);
    int lane = threadIdx.x & 31;
    int b = w / NHEADS, h = w % NHEADS;
    const float* qp = g_qkv;
    const float* kp = g_qkv + GBH;
    const float* vp = g_qkv + 2*GBH;
    int gq = lane >> 2, kk = lane & 3;
    float s = 0.0f;
    if (lane < 16) {
        const float* qr = qp + (gq*BB + b)*HH + h*HD;
        const float* kr = kp + (kk*BB + b)*HH + h*HD;
#pragma unroll
        for (int d = 0; d < HD; d++) s += qr[d]*kr[d];
        s *= 0.25f;
    }
    float m = s;
    m = fmaxf(m, __shfl_xor_sync(~0u, m, 1));
    m = fmaxf(m, __shfl_xor_sync(~0u, m, 2));
    float ev = expf(s - m);
    float sum = ev;
    sum += __shfl_xor_sync(~0u, sum, 1);
    sum += __shfl_xor_sync(~0u, sum, 2);
    float p = ev / sum;
    int g2 = lane >> 3, d0 = (lane & 7)*2;
    float c0 = 0.0f, c1 = 0.0f;
#pragma unroll
    for (int k2 = 0; k2 < 4; k2++) {
        float pv = __shfl_sync(~0u, p, g2*4 + k2);
        const float* vr = vp + (k2*BB + b)*HH + h*HD;
        c0 += pv*vr[d0];
        c1 += pv*vr[d0+1];
    }
    g_ctx[(g2*BB + b)*HH + h*HD + d0]     = c0;
    g_ctx[(g2*BB + b)*HH + h*HD + d0 + 1] = c1;
}
__global__ void k_attnout(const float* __restrict__ ow, const float* __restrict__ ob) {
    __shared__ float cs[HH];
    int g = blockIdx.x;
    int tid = threadIdx.x;
    float bo = ob[tid];
    float acc = 0.0f;
    for (int b = 0; b < BB; b++) {
        __syncthreads();
        cs[tid] = g_ctx[(g*BB + b)*HH + tid];
        __syncthreads();
        float s = bo;
        const float* wr = ow + (size_t)tid*HH;
#pragma unroll 8
        for (int j = 0; j < HH; j++) s += cs[j]*wr[j];
        acc += s;
    }
    g_pooled[g*HH + tid] = acc * (1.0f/BB);
}

// ---------------- final linear ------------------------------------------------------
__global__ void k_final(const float* __restrict__ lw, const float* __restrict__ lb,
                        float* __restrict__ out) {
    __shared__ float ps[GG*HH];
    int tid = threadIdx.x;
    for (int i = tid; i < GG*HH; i += 256) ps[i] = g_pooled[i];
    __syncthreads();
    int n = blockIdx.x*8 + (tid >> 5);
    if (n >= NNODES) return;
    int lane = tid & 31;
    float4 lv = *(const float4*)(lw + (size_t)n*HH + lane*4);
    float d[GG];
#pragma unroll
    for (int g = 0; g < GG; g++) {
        const float* pg = ps + g*HH + lane*4;
        d[g] = lv.x*pg[0] + lv.y*pg[1] + lv.z*pg[2] + lv.w*pg[3];
    }
#pragma unroll
    for (int g = 0; g < GG; g++)
        for (int off = 16; off; off >>= 1)
            d[g] += __shfl_xor_sync(~0u, d[g], off);
    if (lane == 0) {
        float bn = lb[n];
#pragma unroll
        for (int g = 0; g < GG; g++)
            out[(size_t)g*NNODES + n] = (d[g] + bn)*60.0f + 50.0f;
    }
}

// ---------------- launch -------------------------------------------------------------
extern "C" void kernel_launch(void* const* d_in, const int* in_sizes, int n_in,
                              void* d_out, int out_size) {
    const float* x   = (const float*)d_in[0];
    const int*   ei  = (const int*)  d_in[1];
    const int*   bat = (const int*)  d_in[2];
    const float* W1  = (const float*)d_in[3];
    const float* b1  = (const float*)d_in[4];
    const float* W2  = (const float*)d_in[5];
    const float* b2  = (const float*)d_in[6];
    const float* ipw = (const float*)d_in[7];
    const float* ipb = (const float*)d_in[8];
    const float* opw = (const float*)d_in[9];
    const float* opb = (const float*)d_in[10];
    const float* lw  = (const float*)d_in[11];
    const float* lb  = (const float*)d_in[12];
    float* out = (float*)d_out;

    float *p_a2;
    __half *p_aggxh, *p_agg2h, *p_w1h, *p_w2h;
    int *p_degi;
    cudaGetSymbolAddress((void**)&p_a2,    g_a2);
    cudaGetSymbolAddress((void**)&p_aggxh, g_aggxh);
    cudaGetSymbolAddress((void**)&p_agg2h, g_agg2h);
    cudaGetSymbolAddress((void**)&p_w1h,   g_w1h);
    cudaGetSymbolAddress((void**)&p_w2h,   g_w2h);
    cudaGetSymbolAddress((void**)&p_degi,  g_degi);

    const int smem1 = (128*(FIN+8) + FIN*(HH+8))*2;   // 35840 B
    const int smem2 = (128*(HH+8) + HH*(HH+8))*2;     // 69632 B
    cudaFuncSetAttribute(k_mmt<FIN, true>, cudaFuncAttributeMaxDynamicSharedMemorySize, smem1);
    cudaFuncSetAttribute(k_mmt<HH, false>, cudaFuncAttributeMaxDynamicSharedMemorySize, smem2);

    // conversions (independent of CSR build)
    k_xcvt<<<(GN*FIN/8 + 255)/256, 256>>>(x);
    k_wcvt<<<(HH*HH + 255)/256, 256>>>(W1, W2);

    // CSR build (shared by both layers)
    cudaMemsetAsync(p_degi, 0, GN*sizeof(int), 0);
    k_count<<<(GE+255)/256, 256>>>(ei);
    k_scan1<<<GG*TILES, 1024>>>();
    k_scan2<<<1, 128>>>();
    k_scan3<<<GG*TILES, 1024>>>();
    k_fill<<<(GE+255)/256, 256>>>(ei);

    // layer 1: gather fp16 x, then tensor-core matmul+relu -> fp16 a1
    k_g1<<<(GN+7)/8, 256>>>();
    k_mmt<FIN, true><<<(GN+127)/128, 256, smem1>>>(p_aggxh, p_w1h, b1, nullptr, GN);

    // layer 2: gather fp16 a1, then tensor-core matmul+relu -> fp32 a2
    k_g2<<<(GN+7)/8, 256>>>();
    k_mmt<HH, false><<<(GN+127)/128, 256, smem2>>>(p_agg2h, p_w2h, b2, p_a2, GN);

    // mean pooling per (graph, bucket)
    k_bounds<<<1, 128>>>(bat);
    k_pool2<<<GG*BB, 256>>>();

    // attention + projections + mean over B
    k_qkv<<<GG*BB, 3*HH>>>(ipw, ipb);
    k_attn<<<32, 256>>>();
    k_attnout<<<GG, HH>>>(opw, opb);

    // final linear + affine
    k_final<<<(NNODES+7)/8, 256>>>(lw, lb, out);
}

// round 6
// speedup vs baseline: 2.2099x; 1.0586x over previous
#include <cuda_runtime.h>
#include <cuda_fp16.h>
#include <stdint.h>
#include <math.h>

#define GG 4
#define NN 50000
#define EE 800000
#define BB 32
#define FIN 64
#define HH 128
#define NHEADS 8
#define HD 16
#define GN (GG*NN)
#define GE (GG*EE)
#define GBH (GG*BB*HH)
#define NNODES 50000
#define TILES 49   // ceil(NN/1024)

// ---------------- scratch (device globals; no allocation allowed) -------------
__device__ __half g_xh[(size_t)GN*FIN];     // fp16 copy of x
__device__ __half g_aggxh[(size_t)GN*FIN];  // layer1 aggregated (fp16)
__device__ __half g_a1h[(size_t)GN*HH];     // relu(layer1) fp16
__device__ __half g_agg2h[(size_t)GN*HH];   // layer2 aggregated (fp16)
__device__ __half g_a2h[(size_t)GN*HH];     // relu(layer2) fp16
__device__ __half g_w1h[FIN*HH];
__device__ __half g_w2h[HH*HH];
__device__ int   g_degi[GN];
__device__ float g_dinv[GN];
__device__ int   g_off[GG*(NN+1)];
__device__ int   g_cur[GN];
__device__ int   g_tsum[GG*TILES];
__device__ int   g_tbase[GG*TILES];
__device__ int2  g_csr[(size_t)GE];         // packed {row, norm-as-int}
__device__ int   g_bstart[GG*(BB+1)];
__device__ float g_emb[GBH];                // pooled means
__device__ float g_qkv[3*GBH];
__device__ float g_ctx[GBH];
__device__ float g_pooled[GG*HH];

// ---------------- mma / ldmatrix helpers ------------------------------------------
__device__ __forceinline__ unsigned cvta_sm(const void* p) {
    return (unsigned)__cvta_generic_to_shared(p);
}
__device__ __forceinline__ void ldmx4(unsigned& r0, unsigned& r1, unsigned& r2, unsigned& r3, unsigned a) {
    asm volatile("ldmatrix.sync.aligned.m8n8.x4.shared.b16 {%0,%1,%2,%3},[%4];"
        : "=r"(r0), "=r"(r1), "=r"(r2), "=r"(r3) : "r"(a));
}
__device__ __forceinline__ void ldmx4t(unsigned& r0, unsigned& r1, unsigned& r2, unsigned& r3, unsigned a) {
    asm volatile("ldmatrix.sync.aligned.m8n8.x4.trans.shared.b16 {%0,%1,%2,%3},[%4];"
        : "=r"(r0), "=r"(r1), "=r"(r2), "=r"(r3) : "r"(a));
}
__device__ __forceinline__ void mma16816(float* d, unsigned a0, unsigned a1, unsigned a2, unsigned a3,
                                         unsigned b0, unsigned b1) {
    asm volatile("mma.sync.aligned.m16n8k16.row.col.f32.f16.f16.f32 "
        "{%0,%1,%2,%3},{%4,%5,%6,%7},{%8,%9},{%0,%1,%2,%3};"
        : "+f"(d[0]), "+f"(d[1]), "+f"(d[2]), "+f"(d[3])
        : "r"(a0), "r"(a1), "r"(a2), "r"(a3), "r"(b0), "r"(b1));
}

// ---------------- fp16x8 helpers ---------------------------------------------------
__device__ __forceinline__ void fma8(float* acc, uint4 hv, float s) {
    __half2* h = (__half2*)&hv;
#pragma unroll
    for (int j = 0; j < 4; j++) {
        float2 f = __half22float2(h[j]);
        acc[2*j]   = fmaf(f.x, s, acc[2*j]);
        acc[2*j+1] = fmaf(f.y, s, acc[2*j+1]);
    }
}
__device__ __forceinline__ uint4 pack8(const float* acc) {
    uint4 o;
    __half2* h = (__half2*)&o;
#pragma unroll
    for (int j = 0; j < 4; j++) h[j] = __floats2half2_rn(acc[2*j], acc[2*j+1]);
    return o;
}

// ---------------- conversions ------------------------------------------------------
__global__ void k_xcvt(const float* __restrict__ x) {
    size_t i = (size_t)blockIdx.x*blockDim.x + threadIdx.x;
    if (i >= (size_t)GN*FIN/8) return;
    const float4* xs = (const float4*)x;
    float4 f0 = xs[2*i], f1 = xs[2*i+1];
    __half2 h0 = __floats2half2_rn(f0.x, f0.y);
    __half2 h1 = __floats2half2_rn(f0.z, f0.w);
    __half2 h2 = __floats2half2_rn(f1.x, f1.y);
    __half2 h3 = __floats2half2_rn(f1.z, f1.w);
    uint4 o = make_uint4(*(unsigned*)&h0, *(unsigned*)&h1, *(unsigned*)&h2, *(unsigned*)&h3);
    ((uint4*)g_xh)[i] = o;
}
__global__ void k_wcvt(const float* __restrict__ W1, const float* __restrict__ W2) {
    int i = blockIdx.x*blockDim.x + threadIdx.x;
    if (i < FIN*HH) g_w1h[i] = __float2half_rn(W1[i]);
    if (i < HH*HH)  g_w2h[i] = __float2half_rn(W2[i]);
}

// ---------------- CSR build ------------------------------------------------------
__global__ void k_count(const int* __restrict__ ei) {
    int idx = blockIdx.x*blockDim.x + threadIdx.x;
    if (idx >= GE) return;
    int g = idx / EE, e = idx - g*EE;
    int col = ei[(size_t)g*2*EE + EE + e];
    atomicAdd(&g_degi[g*NN + col], 1);
}
__global__ void k_scan1() {
    int g = blockIdx.x / TILES, t = blockIdx.x % TILES;
    int tid = threadIdx.x, lane = tid & 31, wid = tid >> 5;
    __shared__ int wtot[32];
    int i = t*1024 + tid;
    int c = (i < NN) ? g_degi[g*NN + i] : 0;
    int v = c;
#pragma unroll
    for (int o = 1; o < 32; o <<= 1) {
        int u = __shfl_up_sync(~0u, v, o);
        if (lane >= o) v += u;
    }
    if (lane == 31) wtot[wid] = v;
    __syncthreads();
    if (wid == 0) {
        int w2 = wtot[lane];
#pragma unroll
        for (int o = 1; o < 32; o <<= 1) {
            int u = __shfl_up_sync(~0u, w2, o);
            if (lane >= o) w2 += u;
        }
        wtot[lane] = w2;
    }
    __syncthreads();
    int excl = (wid > 0 ? wtot[wid-1] : 0) + v - c;
    if (i < NN) {
        g_off[g*(NN+1) + i] = excl;
        g_dinv[g*NN + i] = rsqrtf((float)(c + 1));
    }
    if (tid == 0) g_tsum[blockIdx.x] = wtot[31];
}
__global__ void k_scan2() {
    int wid = threadIdx.x >> 5, lane = threadIdx.x & 31;
    if (wid >= GG) return;
    int v0 = g_tsum[wid*TILES + lane];
    int v1 = (32 + lane < TILES) ? g_tsum[wid*TILES + 32 + lane] : 0;
    int s0 = v0;
#pragma unroll
    for (int o = 1; o < 32; o <<= 1) {
        int u = __shfl_up_sync(~0u, s0, o);
        if (lane >= o) s0 += u;
    }
    int tot0 = __shfl_sync(~0u, s0, 31);
    int s1 = v1;
#pragma unroll
    for (int o = 1; o < 32; o <<= 1) {
        int u = __shfl_up_sync(~0u, s1, o);
        if (lane >= o) s1 += u;
    }
    s1 += tot0;
    g_tbase[wid*TILES + lane] = s0 - v0;
    if (32 + lane < TILES) g_tbase[wid*TILES + 32 + lane] = s1 - v1;
}
__global__ void k_scan3() {
    int g = blockIdx.x / TILES, t = blockIdx.x % TILES;
    int i = t*1024 + threadIdx.x;
    if (i < NN) {
        int o = g_off[g*(NN+1) + i] + g_tbase[blockIdx.x];
        g_off[g*(NN+1) + i] = o;
        g_cur[g*NN + i] = o;
    }
    if (blockIdx.x == 0 && threadIdx.x < GG)
        g_off[threadIdx.x*(NN+1) + NN] = EE;
}
__global__ void k_fill(const int* __restrict__ ei) {
    int idx = blockIdx.x*blockDim.x + threadIdx.x;
    if (idx >= GE) return;
    int g = idx / EE, e = idx - g*EE;
    const int* bp = ei + (size_t)g*2*EE;
    int row = bp[e], col = bp[EE + e];
    float norm = g_dinv[g*NN + row] * g_dinv[g*NN + col];
    int pos = atomicAdd(&g_cur[g*NN + col], 1);
    g_csr[(size_t)g*EE + pos] = make_int2(row, __float_as_int(norm));
}

// ---------------- CSR gather aggregation ------------------------------------------
// layer 1: 8 lanes per node (4 nodes/warp); each lane loads 16B (8 halfs); 2-unroll
__global__ void __launch_bounds__(256) k_g1() {
    int w = blockIdx.x*32 + (threadIdx.x >> 3);
    if (w >= GN) return;
    int g = w / NN, n = w - g*NN;
    int l8 = threadIdx.x & 7;
    const __half* xg = g_xh + (size_t)g*NN*FIN;
    float di = g_dinv[w], d2 = di*di;
    float acc[8];
#pragma unroll
    for (int j = 0; j < 8; j++) acc[j] = 0.f;
    fma8(acc, *(const uint4*)(xg + (size_t)n*FIN + l8*8), d2);
    int s = g_off[g*(NN+1) + n], e2 = g_off[g*(NN+1) + n + 1];
    const int2* cs = g_csr + (size_t)g*EE;
    int i = s;
    for (; i + 1 < e2; i += 2) {
        int2 r0 = __ldg(&cs[i]);
        int2 r1 = __ldg(&cs[i+1]);
        uint4 a = *(const uint4*)(xg + (size_t)r0.x*FIN + l8*8);
        uint4 b = *(const uint4*)(xg + (size_t)r1.x*FIN + l8*8);
        fma8(acc, a, __int_as_float(r0.y));
        fma8(acc, b, __int_as_float(r1.y));
    }
    if (i < e2) {
        int2 r0 = __ldg(&cs[i]);
        fma8(acc, *(const uint4*)(xg + (size_t)r0.x*FIN + l8*8), __int_as_float(r0.y));
    }
    *(uint4*)(g_aggxh + (size_t)w*FIN + l8*8) = pack8(acc);
}

// layer 2: 16 lanes per node (2 nodes/warp); each lane loads 16B; 2-unroll
__global__ void __launch_bounds__(256) k_g2() {
    int w = blockIdx.x*16 + (threadIdx.x >> 4);
    if (w >= GN) return;
    int g = w / NN, n = w - g*NN;
    int l16 = threadIdx.x & 15;
    const __half* ag = g_a1h + (size_t)g*NN*HH;
    float di = g_dinv[w], d2 = di*di;
    float acc[8];
#pragma unroll
    for (int j = 0; j < 8; j++) acc[j] = 0.f;
    fma8(acc, *(const uint4*)(ag + (size_t)n*HH + l16*8), d2);
    int s = g_off[g*(NN+1) + n], e2 = g_off[g*(NN+1) + n + 1];
    const int2* cs = g_csr + (size_t)g*EE;
    int i = s;
    for (; i + 1 < e2; i += 2) {
        int2 r0 = __ldg(&cs[i]);
        int2 r1 = __ldg(&cs[i+1]);
        uint4 a = *(const uint4*)(ag + (size_t)r0.x*HH + l16*8);
        uint4 b = *(const uint4*)(ag + (size_t)r1.x*HH + l16*8);
        fma8(acc, a, __int_as_float(r0.y));
        fma8(acc, b, __int_as_float(r1.y));
    }
    if (i < e2) {
        int2 r0 = __ldg(&cs[i]);
        fma8(acc, *(const uint4*)(ag + (size_t)r0.x*HH + l16*8), __int_as_float(r0.y));
    }
    *(uint4*)(g_agg2h + (size_t)w*HH + l16*8) = pack8(acc);
}

// ---------------- tensor-core matmul: relu(in[rows,K] @ W[K,128] + b) -> fp16 ------
// 256 threads = 8 warps; block tile 128 rows x 128 cols; fp16 in/out, fp32 accum.
template<int K>
__global__ void __launch_bounds__(256) k_mmt(const __half* __restrict__ in,
        const __half* __restrict__ Wh, const float* __restrict__ bias,
        __half* __restrict__ hout, int rows) {
    constexpr int AS = K + 8;      // padded A row (halfs): odd 16B-unit stride
    constexpr int WS = HH + 8;     // 136
    extern __shared__ __half smh[];
    __half* As = smh;              // 128 * AS
    __half* Ws = smh + 128*AS;     // K * WS
    int tid = threadIdx.x;
    int wid = tid >> 5, lane = tid & 31;
    int base = blockIdx.x * 128;

    for (int idx = tid; idx < K*16; idx += 256) {
        int r = idx >> 4, c8 = (idx & 15) << 3;
        *(uint4*)(Ws + r*WS + c8) = *(const uint4*)(Wh + r*HH + c8);
    }
    for (int idx = tid; idx < 128*(K/8); idx += 256) {
        int r = idx/(K/8), c8 = (idx%(K/8))*8;
        int node = base + r;
        uint4 v = make_uint4(0u,0u,0u,0u);
        if (node < rows) v = *(const uint4*)(in + (size_t)node*K + c8);
        *(uint4*)(As + r*AS + c8) = v;
    }
    __syncthreads();

    float d[16][4];
#pragma unroll
    for (int t = 0; t < 16; t++) {
        d[t][0] = 0.f; d[t][1] = 0.f; d[t][2] = 0.f; d[t][3] = 0.f;
    }

    unsigned a_sm = cvta_sm(As);
    unsigned w_sm = cvta_sm(Ws);
    int arow = wid*16 + (lane & 15);
    int asel = (lane >> 4) * 8;
    int krow = lane & 15;

    for (int kk = 0; kk < K/16; kk++) {
        unsigned a0, a1, a2, a3;
        ldmx4(a0, a1, a2, a3, a_sm + (unsigned)(arow*AS + kk*16 + asel)*2u);
#pragma unroll
        for (int nt = 0; nt < 8; nt++) {
            unsigned b0, b1, b2, b3;
            ldmx4t(b0, b1, b2, b3, w_sm + (unsigned)((kk*16 + krow)*WS + nt*16 + asel)*2u);
            mma16816(d[2*nt],   a0, a1, a2, a3, b0, b1);
            mma16816(d[2*nt+1], a0, a1, a2, a3, b2, b3);
        }
    }

    int gq = lane >> 2, tq = lane & 3;
    int row0 = base + wid*16 + gq;
    int row1 = row0 + 8;
#pragma unroll
    for (int nt = 0; nt < 16; nt++) {
        int c0 = nt*8 + tq*2;
        float2 bc = *(const float2*)(bias + c0);
        float v00 = fmaxf(d[nt][0] + bc.x, 0.f);
        float v01 = fmaxf(d[nt][1] + bc.y, 0.f);
        float v10 = fmaxf(d[nt][2] + bc.x, 0.f);
        float v11 = fmaxf(d[nt][3] + bc.y, 0.f);
        __half2 h0 = __floats2half2_rn(v00, v01);
        __half2 h1 = __floats2half2_rn(v10, v11);
        if (row0 < rows) *(unsigned*)(hout + (size_t)row0*HH + c0) = *(unsigned*)&h0;
        if (row1 < rows) *(unsigned*)(hout + (size_t)row1*HH + c0) = *(unsigned*)&h1;
    }
}

// ---------------- pooling --------------------------------------------------------
__global__ void k_bounds(const int* __restrict__ batch) {
    int tid = threadIdx.x;
    if (tid >= GG*BB) return;
    int g = tid >> 5, b = tid & 31;
    const int* bt = batch + (size_t)g*NN;
    int lo = 0, hi = NN;
    while (lo < hi) {
        int mid = (lo + hi) >> 1;
        if (bt[mid] < b) lo = mid + 1; else hi = mid;
    }
    g_bstart[g*(BB+1) + b] = lo;
    if (b == 0) g_bstart[g*(BB+1) + BB] = NN;
}
__global__ void __launch_bounds__(256) k_pool2() {
    int g = blockIdx.x / BB, b = blockIdx.x % BB;
    int s = g_bstart[g*(BB+1) + b], e = g_bstart[g*(BB+1) + b + 1];
    int cnt = e - s;
    int tid = threadIdx.x;
    int cg = tid & 31, r0 = tid >> 5;
    float4 acc = make_float4(0.f, 0.f, 0.f, 0.f);
    const uint2* a2 = (const uint2*)(g_a2h + (size_t)g*NN*HH);
    for (int n = s + r0; n < e; n += 8) {
        uint2 v = a2[(size_t)n*32 + cg];
        __half2 h0 = *(__half2*)&v.x, h1 = *(__half2*)&v.y;
        float2 f0 = __half22float2(h0), f1 = __half22float2(h1);
        acc.x += f0.x; acc.y += f0.y; acc.z += f1.x; acc.w += f1.y;
    }
    __shared__ float4 sacc[256];
    sacc[tid] = acc;
    __syncthreads();
    if (tid < 32) {
        float4 t = sacc[tid];
#pragma unroll
        for (int r = 1; r < 8; r++) {
            float4 o = sacc[tid + 32*r];
            t.x += o.x; t.y += o.y; t.z += o.z; t.w += o.w;
        }
        float inv = (cnt > 0) ? 1.0f/(float)cnt : 0.0f;
        *(float4*)(g_emb + (size_t)blockIdx.x*HH + tid*4) =
            make_float4(t.x*inv, t.y*inv, t.z*inv, t.w*inv);
    }
}

// ---------------- attention -------------------------------------------------------
__global__ void k_qkv(const float* __restrict__ ipw, const float* __restrict__ ipb) {
    __shared__ float e[HH];
    int rowi = blockIdx.x;
    int tid = threadIdx.x;
    if (tid < HH) e[tid] = g_emb[rowi*HH + tid];
    __syncthreads();
    float s = ipb[tid];
    const float* w = ipw + (size_t)tid*HH;
#pragma unroll 8
    for (int j = 0; j < HH; j++) s += e[j]*w[j];
    int sec = tid >> 7;
    int i = tid & 127;
    g_qkv[sec*GBH + rowi*HH + i] = s;
}
__global__ void k_attn() {
    int w = blockIdx.x*8 + (threadIdx.x >> 5);
    int lane = threadIdx.x & 31;
    int b = w / NHEADS, h = w % NHEADS;
    const float* qp = g_qkv;
    const float* kp = g_qkv + GBH;
    const float* vp = g_qkv + 2*GBH;
    int gq = lane >> 2, kk = lane & 3;
    float s = 0.0f;
    if (lane < 16) {
        const float* qr = qp + (gq*BB + b)*HH + h*HD;
        const float* kr = kp + (kk*BB + b)*HH + h*HD;
#pragma unroll
        for (int d = 0; d < HD; d++) s += qr[d]*kr[d];
        s *= 0.25f;
    }
    float m = s;
    m = fmaxf(m, __shfl_xor_sync(~0u, m, 1));
    m = fmaxf(m, __shfl_xor_sync(~0u, m, 2));
    float ev = expf(s - m);
    float sum = ev;
    sum += __shfl_xor_sync(~0u, sum, 1);
    sum += __shfl_xor_sync(~0u, sum, 2);
    float p = ev / sum;
    int g2 = lane >> 3, d0 = (lane & 7)*2;
    float c0 = 0.0f, c1 = 0.0f;
#pragma unroll
    for (int k2 = 0; k2 < 4; k2++) {
        float pv = __shfl_sync(~0u, p, g2*4 + k2);
        const float* vr = vp + (k2*BB + b)*HH + h*HD;
        c0 += pv*vr[d0];
        c1 += pv*vr[d0+1];
    }
    g_ctx[(g2*BB + b)*HH + h*HD + d0]     = c0;
    g_ctx[(g2*BB + b)*HH + h*HD + d0 + 1] = c1;
}
__global__ void k_attnout(const float* __restrict__ ow, const float* __restrict__ ob) {
    __shared__ float cs[HH];
    int g = blockIdx.x;
    int tid = threadIdx.x;
    float bo = ob[tid];
    float acc = 0.0f;
    for (int b = 0; b < BB; b++) {
        __syncthreads();
        cs[tid] = g_ctx[(g*BB + b)*HH + tid];
        __syncthreads();
        float s = bo;
        const float* wr = ow + (size_t)tid*HH;
#pragma unroll 8
        for (int j = 0; j < HH; j++) s += cs[j]*wr[j];
        acc += s;
    }
    g_pooled[g*HH + tid] = acc * (1.0f/BB);
}

// ---------------- final linear ------------------------------------------------------
__global__ void k_final(const float* __restrict__ lw, const float* __restrict__ lb,
                        float* __restrict__ out) {
    __shared__ float ps[GG*HH];
    int tid = threadIdx.x;
    for (int i = tid; i < GG*HH; i += 256) ps[i] = g_pooled[i];
    __syncthreads();
    int n = blockIdx.x*8 + (tid >> 5);
    if (n >= NNODES) return;
    int lane = tid & 31;
    float4 lv = *(const float4*)(lw + (size_t)n*HH + lane*4);
    float d[GG];
#pragma unroll
    for (int g = 0; g < GG; g++) {
        const float* pg = ps + g*HH + lane*4;
        d[g] = lv.x*pg[0] + lv.y*pg[1] + lv.z*pg[2] + lv.w*pg[3];
    }
#pragma unroll
    for (int g = 0; g < GG; g++)
        for (int off = 16; off; off >>= 1)
            d[g] += __shfl_xor_sync(~0u, d[g], off);
    if (lane == 0) {
        float bn = lb[n];
#pragma unroll
        for (int g = 0; g < GG; g++)
            out[(size_t)g*NNODES + n] = (d[g] + bn)*60.0f + 50.0f;
    }
}

// ---------------- launch -------------------------------------------------------------
extern "C" void kernel_launch(void* const* d_in, const int* in_sizes, int n_in,
                              void* d_out, int out_size) {
    const float* x   = (const float*)d_in[0];
    const int*   ei  = (const int*)  d_in[1];
    const int*   bat = (const int*)  d_in[2];
    const float* W1  = (const float*)d_in[3];
    const float* b1  = (const float*)d_in[4];
    const float* W2  = (const float*)d_in[5];
    const float* b2  = (const float*)d_in[6];
    const float* ipw = (const float*)d_in[7];
    const float* ipb = (const float*)d_in[8];
    const float* opw = (const float*)d_in[9];
    const float* opb = (const float*)d_in[10];
    const float* lw  = (const float*)d_in[11];
    const float* lb  = (const float*)d_in[12];
    float* out = (float*)d_out;

    __half *p_aggxh, *p_agg2h, *p_a1h, *p_a2h, *p_w1h, *p_w2h;
    int *p_degi;
    cudaGetSymbolAddress((void**)&p_aggxh, g_aggxh);
    cudaGetSymbolAddress((void**)&p_agg2h, g_agg2h);
    cudaGetSymbolAddress((void**)&p_a1h,   g_a1h);
    cudaGetSymbolAddress((void**)&p_a2h,   g_a2h);
    cudaGetSymbolAddress((void**)&p_w1h,   g_w1h);
    cudaGetSymbolAddress((void**)&p_w2h,   g_w2h);
    cudaGetSymbolAddress((void**)&p_degi,  g_degi);

    const int smem1 = (128*(FIN+8) + FIN*(HH+8))*2;   // 35840 B
    const int smem2 = (128*(HH+8) + HH*(HH+8))*2;     // 69632 B
    cudaFuncSetAttribute(k_mmt<FIN>, cudaFuncAttributeMaxDynamicSharedMemorySize, smem1);
    cudaFuncSetAttribute(k_mmt<HH>,  cudaFuncAttributeMaxDynamicSharedMemorySize, smem2);

    // conversions (independent of CSR build)
    k_xcvt<<<(GN*FIN/8 + 255)/256, 256>>>(x);
    k_wcvt<<<(HH*HH + 255)/256, 256>>>(W1, W2);

    // CSR build (shared by both layers)
    cudaMemsetAsync(p_degi, 0, GN*sizeof(int), 0);
    k_count<<<(GE+255)/256, 256>>>(ei);
    k_scan1<<<GG*TILES, 1024>>>();
    k_scan2<<<1, 128>>>();
    k_scan3<<<GG*TILES, 1024>>>();
    k_fill<<<(GE+255)/256, 256>>>(ei);

    // layer 1: gather fp16 x, then tensor-core matmul+relu -> fp16 a1
    k_g1<<<(GN+31)/32, 256>>>();
    k_mmt<FIN><<<(GN+127)/128, 256, smem1>>>(p_aggxh, p_w1h, b1, p_a1h, GN);

    // layer 2: gather fp16 a1, then tensor-core matmul+relu -> fp16 a2
    k_g2<<<(GN+15)/16, 256>>>();
    k_mmt<HH><<<(GN+127)/128, 256, smem2>>>(p_agg2h, p_w2h, b2, p_a2h, GN);

    // mean pooling per (graph, bucket)
    k_bounds<<<1, 128>>>(bat);
    k_pool2<<<GG*BB, 256>>>();

    // attention + projections + mean over B
    k_qkv<<<GG*BB, 3*HH>>>(ipw, ipb);
    k_attn<<<32, 256>>>();
    k_attnout<<<GG, HH>>>(opw, opb);

    // final linear + affine
    k_final<<<(NNODES+7)/8, 256>>>(lw, lb, out);
}

// round 7
// speedup vs baseline: 2.8960x; 1.3105x over previous
#include <cuda_runtime.h>
#include <cuda_fp16.h>
#include <stdint.h>
#include <math.h>

#define GG 4
#define NN 50000
#define EE 800000
#define BB 32
#define FIN 64
#define HH 128
#define NHEADS 8
#define HD 16
#define GN (GG*NN)
#define GE (GG*EE)
#define GBH (GG*BB*HH)
#define NNODES 50000
#define TILES 49   // ceil(NN/1024)

// ---------------- scratch (device globals; no allocation allowed) -------------
__device__ __half g_xh[(size_t)GN*FIN];     // fp16 copy of x
__device__ __half g_a1h[(size_t)GN*HH];     // relu(layer1) fp16
__device__ __half g_a2h[(size_t)GN*HH];     // relu(layer2) fp16
__device__ __half g_w1h[FIN*HH];
__device__ __half g_w2h[HH*HH];
__device__ int   g_degi[GN];
__device__ float g_dinv[GN];
__device__ int   g_off[GG*(NN+1)];
__device__ int   g_cur[GN];
__device__ int   g_tsum[GG*TILES];
__device__ int   g_tbase[GG*TILES];
__device__ unsigned g_csr[(size_t)GE];      // packed {norm-fp16:hi16, row-u16:lo16}
__device__ int   g_bstart[GG*(BB+1)];
__device__ float g_emb[GBH];                // pooled means
__device__ float g_pooled[GG*HH];

// ---------------- mma / ldmatrix helpers ------------------------------------------
__device__ __forceinline__ unsigned cvta_sm(const void* p) {
    return (unsigned)__cvta_generic_to_shared(p);
}
__device__ __forceinline__ void ldmx4(unsigned& r0, unsigned& r1, unsigned& r2, unsigned& r3, unsigned a) {
    asm volatile("ldmatrix.sync.aligned.m8n8.x4.shared.b16 {%0,%1,%2,%3},[%4];"
        : "=r"(r0), "=r"(r1), "=r"(r2), "=r"(r3) : "r"(a));
}
__device__ __forceinline__ void ldmx4t(unsigned& r0, unsigned& r1, unsigned& r2, unsigned& r3, unsigned a) {
    asm volatile("ldmatrix.sync.aligned.m8n8.x4.trans.shared.b16 {%0,%1,%2,%3},[%4];"
        : "=r"(r0), "=r"(r1), "=r"(r2), "=r"(r3) : "r"(a));
}
__device__ __forceinline__ void mma16816(float* d, unsigned a0, unsigned a1, unsigned a2, unsigned a3,
                                         unsigned b0, unsigned b1) {
    asm volatile("mma.sync.aligned.m16n8k16.row.col.f32.f16.f16.f32 "
        "{%0,%1,%2,%3},{%4,%5,%6,%7},{%8,%9},{%0,%1,%2,%3};"
        : "+f"(d[0]), "+f"(d[1]), "+f"(d[2]), "+f"(d[3])
        : "r"(a0), "r"(a1), "r"(a2), "r"(a3), "r"(b0), "r"(b1));
}

// ---------------- conversions ------------------------------------------------------
__global__ void k_xcvt(const float* __restrict__ x) {
    size_t i = (size_t)blockIdx.x*blockDim.x + threadIdx.x;
    if (i >= (size_t)GN*FIN/8) return;
    const float4* xs = (const float4*)x;
    float4 f0 = xs[2*i], f1 = xs[2*i+1];
    __half2 h0 = __floats2half2_rn(f0.x, f0.y);
    __half2 h1 = __floats2half2_rn(f0.z, f0.w);
    __half2 h2 = __floats2half2_rn(f1.x, f1.y);
    __half2 h3 = __floats2half2_rn(f1.z, f1.w);
    uint4 o = make_uint4(*(unsigned*)&h0, *(unsigned*)&h1, *(unsigned*)&h2, *(unsigned*)&h3);
    ((uint4*)g_xh)[i] = o;
}
__global__ void k_wcvt(const float* __restrict__ W1, const float* __restrict__ W2) {
    int i = blockIdx.x*blockDim.x + threadIdx.x;
    if (i < FIN*HH) g_w1h[i] = __float2half_rn(W1[i]);
    if (i < HH*HH)  g_w2h[i] = __float2half_rn(W2[i]);
}

// ---------------- CSR build ------------------------------------------------------
__global__ void k_count(const int* __restrict__ ei) {
    int idx = blockIdx.x*blockDim.x + threadIdx.x;
    if (idx >= GE) return;
    int g = idx / EE, e = idx - g*EE;
    int col = ei[(size_t)g*2*EE + EE + e];
    atomicAdd(&g_degi[g*NN + col], 1);
}
__global__ void k_scan1() {
    int g = blockIdx.x / TILES, t = blockIdx.x % TILES;
    int tid = threadIdx.x, lane = tid & 31, wid = tid >> 5;
    __shared__ int wtot[32];
    int i = t*1024 + tid;
    int c = (i < NN) ? g_degi[g*NN + i] : 0;
    int v = c;
#pragma unroll
    for (int o = 1; o < 32; o <<= 1) {
        int u = __shfl_up_sync(~0u, v, o);
        if (lane >= o) v += u;
    }
    if (lane == 31) wtot[wid] = v;
    __syncthreads();
    if (wid == 0) {
        int w2 = wtot[lane];
#pragma unroll
        for (int o = 1; o < 32; o <<= 1) {
            int u = __shfl_up_sync(~0u, w2, o);
            if (lane >= o) w2 += u;
        }
        wtot[lane] = w2;
    }
    __syncthreads();
    int excl = (wid > 0 ? wtot[wid-1] : 0) + v - c;
    if (i < NN) {
        g_off[g*(NN+1) + i] = excl;
        g_dinv[g*NN + i] = rsqrtf((float)(c + 1));
    }
    if (tid == 0) g_tsum[blockIdx.x] = wtot[31];
}
__global__ void k_scan2() {
    int wid = threadIdx.x >> 5, lane = threadIdx.x & 31;
    if (wid >= GG) return;
    int v0 = g_tsum[wid*TILES + lane];
    int v1 = (32 + lane < TILES) ? g_tsum[wid*TILES + 32 + lane] : 0;
    int s0 = v0;
#pragma unroll
    for (int o = 1; o < 32; o <<= 1) {
        int u = __shfl_up_sync(~0u, s0, o);
        if (lane >= o) s0 += u;
    }
    int tot0 = __shfl_sync(~0u, s0, 31);
    int s1 = v1;
#pragma unroll
    for (int o = 1; o < 32; o <<= 1) {
        int u = __shfl_up_sync(~0u, s1, o);
        if (lane >= o) s1 += u;
    }
    s1 += tot0;
    g_tbase[wid*TILES + lane] = s0 - v0;
    if (32 + lane < TILES) g_tbase[wid*TILES + 32 + lane] = s1 - v1;
}
__global__ void k_scan3() {
    int g = blockIdx.x / TILES, t = blockIdx.x % TILES;
    int i = t*1024 + threadIdx.x;
    if (i < NN) {
        int o = g_off[g*(NN+1) + i] + g_tbase[blockIdx.x];
        g_off[g*(NN+1) + i] = o;
        g_cur[g*NN + i] = o;
    }
    if (blockIdx.x == 0 && threadIdx.x < GG)
        g_off[threadIdx.x*(NN+1) + NN] = EE;
}
__global__ void k_fill(const int* __restrict__ ei) {
    int idx = blockIdx.x*blockDim.x + threadIdx.x;
    if (idx >= GE) return;
    int g = idx / EE, e = idx - g*EE;
    const int* bp = ei + (size_t)g*2*EE;
    int row = bp[e], col = bp[EE + e];
    float norm = g_dinv[g*NN + row] * g_dinv[g*NN + col];
    unsigned rec = (unsigned)row |
        ((unsigned)__half_as_ushort(__float2half_rn(norm)) << 16);
    int pos = atomicAdd(&g_cur[g*NN + col], 1);
    g_csr[(size_t)g*EE + pos] = rec;
}

// ---------------- fused gather + tensor-core matmul per layer ----------------------
// relu( (D^-1/2 A D^-1/2 + selfloop) src @ W + b ) -> fp16 hout
// 256 threads; block handles 128 nodes; warp w gathers nodes w*16..w*16+15 into smem,
// then the block does a 128x128 mma.
template<int K>
__global__ void __launch_bounds__(256) k_fused(const __half* __restrict__ src,
        const __half* __restrict__ Wh, const float* __restrict__ bias,
        __half* __restrict__ hout) {
    constexpr int AS = K + 8;      // padded A row (halfs)
    constexpr int WS = HH + 8;     // 136
    extern __shared__ __half smh[];
    __half* As = smh;              // 128 * AS
    __half* Ws = smh + 128*AS;     // K * WS
    int tid = threadIdx.x, wid = tid >> 5, lane = tid & 31;
    int base = blockIdx.x * 128;

    // load W tile
    for (int idx = tid; idx < K*16; idx += 256) {
        int r = idx >> 4, c8 = (idx & 15) << 3;
        *(uint4*)(Ws + r*WS + c8) = *(const uint4*)(Wh + r*HH + c8);
    }

    // gather phase: warp handles 16 local rows
    for (int t = 0; t < 16; t++) {
        int rl = wid*16 + t;
        int w = base + rl;
        if (w < GN) {
            int g = w / NN, n = w - g*NN;
            const __half* xg = src + (size_t)g*NN*K;
            float di = g_dinv[w], d2 = di*di;
            int s = g_off[g*(NN+1) + n], e2 = g_off[g*(NN+1) + n + 1];
            const unsigned* cs = g_csr + (size_t)g*EE;
            if (K == FIN) {
                // lane covers 2 halfs (4B)
                float a0, a1;
                {
                    __half2 h = *(const __half2*)(xg + (size_t)n*K + lane*2);
                    float2 f = __half22float2(h);
                    a0 = f.x*d2; a1 = f.y*d2;
                }
                int i = s;
                for (; i + 1 < e2; i += 2) {
                    unsigned r0 = __ldg(&cs[i]), r1 = __ldg(&cs[i+1]);
                    float n0 = __half2float(__ushort_as_half((unsigned short)(r0 >> 16)));
                    float n1 = __half2float(__ushort_as_half((unsigned short)(r1 >> 16)));
                    __half2 ha = *(const __half2*)(xg + (size_t)(r0 & 0xFFFFu)*K + lane*2);
                    __half2 hb = *(const __half2*)(xg + (size_t)(r1 & 0xFFFFu)*K + lane*2);
                    float2 fa = __half22float2(ha), fb = __half22float2(hb);
                    a0 = fmaf(fa.x, n0, fmaf(fb.x, n1, a0));
                    a1 = fmaf(fa.y, n0, fmaf(fb.y, n1, a1));
                }
                if (i < e2) {
                    unsigned r0 = __ldg(&cs[i]);
                    float n0 = __half2float(__ushort_as_half((unsigned short)(r0 >> 16)));
                    __half2 ha = *(const __half2*)(xg + (size_t)(r0 & 0xFFFFu)*K + lane*2);
                    float2 fa = __half22float2(ha);
                    a0 = fmaf(fa.x, n0, a0);
                    a1 = fmaf(fa.y, n0, a1);
                }
                *(__half2*)(As + rl*AS + lane*2) = __floats2half2_rn(a0, a1);
            } else {
                // K == HH: lane covers 4 halfs (8B)
                float a0, a1, a2, a3;
                {
                    uint2 hv = *(const uint2*)(xg + (size_t)n*K + lane*4);
                    float2 f0 = __half22float2(*(__half2*)&hv.x);
                    float2 f1 = __half22float2(*(__half2*)&hv.y);
                    a0 = f0.x*d2; a1 = f0.y*d2; a2 = f1.x*d2; a3 = f1.y*d2;
                }
                int i = s;
                for (; i + 1 < e2; i += 2) {
                    unsigned r0 = __ldg(&cs[i]), r1 = __ldg(&cs[i+1]);
                    float n0 = __half2float(__ushort_as_half((unsigned short)(r0 >> 16)));
                    float n1 = __half2float(__ushort_as_half((unsigned short)(r1 >> 16)));
                    uint2 va = *(const uint2*)(xg + (size_t)(r0 & 0xFFFFu)*K + lane*4);
                    uint2 vb = *(const uint2*)(xg + (size_t)(r1 & 0xFFFFu)*K + lane*4);
                    float2 fa0 = __half22float2(*(__half2*)&va.x);
                    float2 fa1 = __half22float2(*(__half2*)&va.y);
                    float2 fb0 = __half22float2(*(__half2*)&vb.x);
                    float2 fb1 = __half22float2(*(__half2*)&vb.y);
                    a0 = fmaf(fa0.x, n0, fmaf(fb0.x, n1, a0));
                    a1 = fmaf(fa0.y, n0, fmaf(fb0.y, n1, a1));
                    a2 = fmaf(fa1.x, n0, fmaf(fb1.x, n1, a2));
                    a3 = fmaf(fa1.y, n0, fmaf(fb1.y, n1, a3));
                }
                if (i < e2) {
                    unsigned r0 = __ldg(&cs[i]);
                    float n0 = __half2float(__ushort_as_half((unsigned short)(r0 >> 16)));
                    uint2 va = *(const uint2*)(xg + (size_t)(r0 & 0xFFFFu)*K + lane*4);
                    float2 fa0 = __half22float2(*(__half2*)&va.x);
                    float2 fa1 = __half22float2(*(__half2*)&va.y);
                    a0 = fmaf(fa0.x, n0, a0);
                    a1 = fmaf(fa0.y, n0, a1);
                    a2 = fmaf(fa1.x, n0, a2);
                    a3 = fmaf(fa1.y, n0, a3);
                }
                uint2 o;
                *(__half2*)&o.x = __floats2half2_rn(a0, a1);
                *(__half2*)&o.y = __floats2half2_rn(a2, a3);
                *(uint2*)(As + rl*AS + lane*4) = o;
            }
        } else {
            if (K == FIN) *(__half2*)(As + rl*AS + lane*2) = __floats2half2_rn(0.f, 0.f);
            else {
                uint2 z = make_uint2(0u, 0u);
                *(uint2*)(As + rl*AS + lane*4) = z;
            }
        }
    }
    __syncthreads();

    // mma phase
    float d[16][4];
#pragma unroll
    for (int t = 0; t < 16; t++) {
        d[t][0] = 0.f; d[t][1] = 0.f; d[t][2] = 0.f; d[t][3] = 0.f;
    }
    unsigned a_sm = cvta_sm(As);
    unsigned w_sm = cvta_sm(Ws);
    int arow = wid*16 + (lane & 15);
    int asel = (lane >> 4) * 8;
    int krow = lane & 15;
    for (int kk = 0; kk < K/16; kk++) {
        unsigned a0, a1, a2, a3;
        ldmx4(a0, a1, a2, a3, a_sm + (unsigned)(arow*AS + kk*16 + asel)*2u);
#pragma unroll
        for (int nt = 0; nt < 8; nt++) {
            unsigned b0, b1, b2, b3;
            ldmx4t(b0, b1, b2, b3, w_sm + (unsigned)((kk*16 + krow)*WS + nt*16 + asel)*2u);
            mma16816(d[2*nt],   a0, a1, a2, a3, b0, b1);
            mma16816(d[2*nt+1], a0, a1, a2, a3, b2, b3);
        }
    }

    // epilogue: bias + relu -> fp16
    int gq = lane >> 2, tq = lane & 3;
    int row0 = base + wid*16 + gq;
    int row1 = row0 + 8;
#pragma unroll
    for (int nt = 0; nt < 16; nt++) {
        int c0 = nt*8 + tq*2;
        float2 bc = *(const float2*)(bias + c0);
        float v00 = fmaxf(d[nt][0] + bc.x, 0.f);
        float v01 = fmaxf(d[nt][1] + bc.y, 0.f);
        float v10 = fmaxf(d[nt][2] + bc.x, 0.f);
        float v11 = fmaxf(d[nt][3] + bc.y, 0.f);
        __half2 h0 = __floats2half2_rn(v00, v01);
        __half2 h1 = __floats2half2_rn(v10, v11);
        if (row0 < GN) *(unsigned*)(hout + (size_t)row0*HH + c0) = *(unsigned*)&h0;
        if (row1 < GN) *(unsigned*)(hout + (size_t)row1*HH + c0) = *(unsigned*)&h1;
    }
}

// ---------------- pooling --------------------------------------------------------
__global__ void k_bounds(const int* __restrict__ batch) {
    int tid = threadIdx.x;
    if (tid >= GG*BB) return;
    int g = tid >> 5, b = tid & 31;
    const int* bt = batch + (size_t)g*NN;
    int lo = 0, hi = NN;
    while (lo < hi) {
        int mid = (lo + hi) >> 1;
        if (bt[mid] < b) lo = mid + 1; else hi = mid;
    }
    g_bstart[g*(BB+1) + b] = lo;
    if (b == 0) g_bstart[g*(BB+1) + BB] = NN;
}
__global__ void __launch_bounds__(256) k_pool2() {
    int g = blockIdx.x / BB, b = blockIdx.x % BB;
    int s = g_bstart[g*(BB+1) + b], e = g_bstart[g*(BB+1) + b + 1];
    int cnt = e - s;
    int tid = threadIdx.x;
    int cg = tid & 31, r0 = tid >> 5;
    float4 acc = make_float4(0.f, 0.f, 0.f, 0.f);
    const uint2* a2 = (const uint2*)(g_a2h + (size_t)g*NN*HH);
    for (int n = s + r0; n < e; n += 8) {
        uint2 v = a2[(size_t)n*32 + cg];
        __half2 h0 = *(__half2*)&v.x, h1 = *(__half2*)&v.y;
        float2 f0 = __half22float2(h0), f1 = __half22float2(h1);
        acc.x += f0.x; acc.y += f0.y; acc.z += f1.x; acc.w += f1.y;
    }
    __shared__ float4 sacc[256];
    sacc[tid] = acc;
    __syncthreads();
    if (tid < 32) {
        float4 t = sacc[tid];
#pragma unroll
        for (int r = 1; r < 8; r++) {
            float4 o = sacc[tid + 32*r];
            t.x += o.x; t.y += o.y; t.z += o.z; t.w += o.w;
        }
        float inv = (cnt > 0) ? 1.0f/(float)cnt : 0.0f;
        *(float4*)(g_emb + (size_t)blockIdx.x*HH + tid*4) =
            make_float4(t.x*inv, t.y*inv, t.z*inv, t.w*inv);
    }
}

// ---------------- fused attention (one block per batch-bucket b) -------------------
__global__ void __launch_bounds__(384) k_attall(const float* __restrict__ ipw,
        const float* __restrict__ ipb, const float* __restrict__ opw,
        const float* __restrict__ opb) {
    __shared__ float emb[GG][HH];
    __shared__ float qkv[3][GG][HH];
    __shared__ float sc[NHEADS][GG][GG];
    __shared__ float att[GG][HH];
    int b = blockIdx.x, tid = threadIdx.x;
    for (int i = tid; i < GG*HH; i += 384) {
        int g = i >> 7, c = i & 127;
        emb[g][c] = g_emb[(g*BB + b)*HH + c];
    }
    __syncthreads();
    // qkv: 1536 outputs, 4 per thread
#pragma unroll
    for (int t = 0; t < 4; t++) {
        int o = tid + t*384;
        int sec = o / 512, rem = o - sec*512, g = rem >> 7, i = rem & 127;
        const float* wrow = ipw + (size_t)(sec*HH + i)*HH;
        float s = ipb[sec*HH + i];
#pragma unroll 8
        for (int j = 0; j < HH; j++) s += emb[g][j]*wrow[j];
        qkv[sec][g][i] = s;
    }
    __syncthreads();
    // scores: 8 heads x 4 q-graphs x 4 k-graphs
    if (tid < 128) {
        int h = tid >> 4, g = (tid >> 2) & 3, k = tid & 3;
        float s = 0.f;
#pragma unroll
        for (int dd = 0; dd < HD; dd++) s += qkv[0][g][h*HD + dd]*qkv[1][k][h*HD + dd];
        sc[h][g][k] = s*0.25f;   // 1/sqrt(HD)
    }
    __syncthreads();
    // softmax over k + ctx
    for (int o = tid; o < GG*HH; o += 384) {
        int g = o >> 7, i = o & 127, h = i >> 4;
        float s0 = sc[h][g][0], s1 = sc[h][g][1], s2 = sc[h][g][2], s3 = sc[h][g][3];
        float m = fmaxf(fmaxf(s0, s1), fmaxf(s2, s3));
        float e0 = expf(s0 - m), e1 = expf(s1 - m), e2 = expf(s2 - m), e3 = expf(s3 - m);
        float inv = 1.f/(e0 + e1 + e2 + e3);
        att[g][i] = (e0*qkv[2][0][i] + e1*qkv[2][1][i] + e2*qkv[2][2][i] + e3*qkv[2][3][i])*inv;
    }
    __syncthreads();
    // out projection + mean over b (atomic accumulate)
    for (int o = tid; o < GG*HH; o += 384) {
        int g = o >> 7, i = o & 127;
        const float* wrow = opw + (size_t)i*HH;
        float s = opb[i];
#pragma unroll 8
        for (int j = 0; j < HH; j++) s += att[g][j]*wrow[j];
        atomicAdd(&g_pooled[g*HH + i], s*(1.0f/BB));
    }
}

// ---------------- final linear ------------------------------------------------------
__global__ void k_final(const float* __restrict__ lw, const float* __restrict__ lb,
                        float* __restrict__ out) {
    __shared__ float ps[GG*HH];
    int tid = threadIdx.x;
    for (int i = tid; i < GG*HH; i += 256) ps[i] = g_pooled[i];
    __syncthreads();
    int n = blockIdx.x*8 + (tid >> 5);
    if (n >= NNODES) return;
    int lane = tid & 31;
    float4 lv = *(const float4*)(lw + (size_t)n*HH + lane*4);
    float d[GG];
#pragma unroll
    for (int g = 0; g < GG; g++) {
        const float* pg = ps + g*HH + lane*4;
        d[g] = lv.x*pg[0] + lv.y*pg[1] + lv.z*pg[2] + lv.w*pg[3];
    }
#pragma unroll
    for (int g = 0; g < GG; g++)
        for (int off = 16; off; off >>= 1)
            d[g] += __shfl_xor_sync(~0u, d[g], off);
    if (lane == 0) {
        float bn = lb[n];
#pragma unroll
        for (int g = 0; g < GG; g++)
            out[(size_t)g*NNODES + n] = (d[g] + bn)*60.0f + 50.0f;
    }
}

// ---------------- launch -------------------------------------------------------------
extern "C" void kernel_launch(void* const* d_in, const int* in_sizes, int n_in,
                              void* d_out, int out_size) {
    const float* x   = (const float*)d_in[0];
    const int*   ei  = (const int*)  d_in[1];
    const int*   bat = (const int*)  d_in[2];
    const float* W1  = (const float*)d_in[3];
    const float* b1  = (const float*)d_in[4];
    const float* W2  = (const float*)d_in[5];
    const float* b2  = (const float*)d_in[6];
    const float* ipw = (const float*)d_in[7];
    const float* ipb = (const float*)d_in[8];
    const float* opw = (const float*)d_in[9];
    const float* opb = (const float*)d_in[10];
    const float* lw  = (const float*)d_in[11];
    const float* lb  = (const float*)d_in[12];
    float* out = (float*)d_out;

    __half *p_xh, *p_a1h, *p_a2h, *p_w1h, *p_w2h;
    int *p_degi;
    float *p_pooled;
    cudaGetSymbolAddress((void**)&p_xh,     g_xh);
    cudaGetSymbolAddress((void**)&p_a1h,    g_a1h);
    cudaGetSymbolAddress((void**)&p_a2h,    g_a2h);
    cudaGetSymbolAddress((void**)&p_w1h,    g_w1h);
    cudaGetSymbolAddress((void**)&p_w2h,    g_w2h);
    cudaGetSymbolAddress((void**)&p_degi,   g_degi);
    cudaGetSymbolAddress((void**)&p_pooled, g_pooled);

    const int smem1 = (128*(FIN+8) + FIN*(HH+8))*2;   // 35840 B
    const int smem2 = (128*(HH+8) + HH*(HH+8))*2;     // 69632 B
    cudaFuncSetAttribute(k_fused<FIN>, cudaFuncAttributeMaxDynamicSharedMemorySize, smem1);
    cudaFuncSetAttribute(k_fused<HH>,  cudaFuncAttributeMaxDynamicSharedMemorySize, smem2);

    // CSR build first (so profiled launch window covers the heavy kernels)
    cudaMemsetAsync(p_degi, 0, GN*sizeof(int), 0);
    cudaMemsetAsync(p_pooled, 0, GG*HH*sizeof(float), 0);
    k_count<<<(GE+255)/256, 256>>>(ei);
    k_scan1<<<GG*TILES, 1024>>>();
    k_scan2<<<1, 128>>>();
    k_scan3<<<GG*TILES, 1024>>>();
    k_fill<<<(GE+255)/256, 256>>>(ei);

    // conversions
    k_xcvt<<<(GN*FIN/8 + 255)/256, 256>>>(x);
    k_wcvt<<<(HH*HH + 255)/256, 256>>>(W1, W2);
    k_bounds<<<1, 128>>>(bat);

    // layer 1 fused: gather x + matmul + relu -> a1 (fp16)
    k_fused<FIN><<<(GN+127)/128, 256, smem1>>>(p_xh, p_w1h, b1, p_a1h);
    // layer 2 fused: gather a1 + matmul + relu -> a2 (fp16)
    k_fused<HH><<<(GN+127)/128, 256, smem2>>>(p_a1h, p_w2h, b2, p_a2h);

    // mean pooling per (graph, bucket)
    k_pool2<<<GG*BB, 256>>>();

    // fused attention + projections + mean over B
    k_attall<<<BB, 384>>>(ipw, ipb, opw, opb);

    // final linear + affine
    k_final<<<(NNODES+7)/8, 256>>>(lw, lb, out);
}